// round 14
// baseline (speedup 1.0000x reference)
#include <cuda_runtime.h>
#include <cuda_fp16.h>
#include <cstdint>

#define NN      256
#define EE      65536
#define MMOT    65536
#define NNZ     524288
#define EENNZ   524288
#define SLOPE   0.01f

// ---------------- device scratch (static, no allocations) ----------------
__device__ int   g_is64;
__device__ int   g_bar[8];             // monotonic grid-barrier counters
__device__ float g_small[7 * 65536];   // A, x, y, G, y2, T1(L scratch), spare
#define OFF_A   0
#define OFF_X   (1 * 65536)
#define OFF_Y   (2 * 65536)
#define OFF_G   (3 * 65536)
#define OFF_Y2  (4 * 65536)
#define OFF_T1  (5 * 65536)
__device__ float   g_Wg2[65536];        // W_gcn @ W_lin2
__device__ __half2 g_WcHi[128 * 64];    // fp16 hi of Wc, packed (k,k+1) pairs
__device__ __half2 g_WcLo[128 * 64];    // fp16 lo residual, same packing
__device__ __half  g_T16[65536];        // fp16 T = y2 @ Wg2
__device__ float   g_b2[256];
__device__ float   g_bc[64];
__device__ float   g_dinv[256];
__device__ float   g_dis[EE];
__device__ int     g_cnt_he[EE];
__device__ int     g_cnt_col[EE];
__device__ int     g_off_he[EE + 1];
__device__ int     g_off_col[EE + 1];
__device__ int     g_cur_he[EE];
__device__ int     g_cur_col[EE];
__device__ int     g_dnode[NN];
__device__ int     g_members[NNZ];
__device__ int     g_rows[EENNZ];
__device__ __half  g_w[(size_t)EE * 256];  // dis[e] * mean-agg rows (fp16, 32 MB)
__device__ __half  g_v[(size_t)EE * 256];  // GCN+lin2 output per hyperedge (fp16, 32 MB)

__device__ __forceinline__ int ldidx(const void* p, long long i, int is64) {
    return is64 ? (int)((const long long*)p)[i] : ((const int*)p)[i];
}
__device__ __forceinline__ float lrelu(float x) { return x >= 0.0f ? x : SLOPE * x; }
__device__ __forceinline__ void mma_f16(float* d,
                                        unsigned a0, unsigned a1, unsigned a2, unsigned a3,
                                        unsigned b0, unsigned b1) {
    asm volatile(
        "mma.sync.aligned.m16n8k16.row.col.f32.f16.f16.f32 "
        "{%0,%1,%2,%3},{%4,%5,%6,%7},{%8,%9},{%0,%1,%2,%3};"
        : "+f"(d[0]), "+f"(d[1]), "+f"(d[2]), "+f"(d[3])
        : "r"(a0), "r"(a1), "r"(a2), "r"(a3), "r"(b0), "r"(b1));
}
// accumulate a 16B fp16 chunk into 8 fp32 accumulators
__device__ __forceinline__ void acc_half8(float* acc, uint4 raw) {
    union { uint4 u; __half2 h[4]; } pk;
    pk.u = raw;
#pragma unroll
    for (int r = 0; r < 4; r++) {
        float2 f = __half22float2(pk.h[r]);
        acc[2 * r]     += f.x;
        acc[2 * r + 1] += f.y;
    }
}

// ---------------- init + index dtype detection (fused) ----------------
__global__ void k_initdet(const unsigned* __restrict__ p) {
    int stride = gridDim.x * blockDim.x;
    for (int t = blockIdx.x * blockDim.x + threadIdx.x; t < EE; t += stride) {
        g_small[OFF_A + t]  = 0.0f;
        g_small[OFF_T1 + t] = 0.0f;
        g_cnt_he[t] = 0; g_cnt_col[t] = 0;
        g_cur_he[t] = 0; g_cur_col[t] = 0;
        if (t < NN) g_dnode[t] = 0;
    }
    if (blockIdx.x == 0) {
        __shared__ int nz;
        if (threadIdx.x == 0) nz = 0;
        __syncthreads();
        int any = 0;
        for (int i = threadIdx.x; i < 4096; i += blockDim.x)
            any |= (p[2 * i + 1] != 0u);
        if (any) atomicOr(&nz, 1);
        __syncthreads();
        if (threadIdx.x == 0) g_is64 = nz ? 0 : 1;
    }
}

// ---------------- fused histograms ----------------
__global__ void k_hist(const void* __restrict__ ei, const void* __restrict__ eei) {
    int is64 = g_is64;
    __shared__ int h[NN];
    if (blockIdx.x < 1024) {
        for (int i = threadIdx.x; i < NN; i += blockDim.x) h[i] = 0;
        __syncthreads();
        int stride = 1024 * blockDim.x;
        for (int i = blockIdx.x * blockDim.x + threadIdx.x; i < NNZ; i += stride) {
            int src = ldidx(ei, i, is64);
            int he  = ldidx(ei, (long long)NNZ + i, is64);
            atomicAdd(&g_cnt_he[he], 1);
            atomicAdd(&h[src], 1);
        }
        __syncthreads();
        for (int i = threadIdx.x; i < NN; i += blockDim.x)
            if (h[i]) atomicAdd(&g_dnode[i], h[i]);
    } else {
        int b = blockIdx.x - 1024;
        int stride = 1024 * blockDim.x;
        for (int j = b * blockDim.x + threadIdx.x; j < EENNZ; j += stride) {
            int col = ldidx(eei, (long long)EENNZ + j, is64);
            atomicAdd(&g_cnt_col[col], 1);
        }
    }
}

// ------- 64K-bin exclusive scan (2 blocks: one per CSR) + degree prep -------
__global__ void k_scan() {
    int which = blockIdx.x;
    const int* cnt = which ? g_cnt_col : g_cnt_he;
    int*       off = which ? g_off_col : g_off_he;
    __shared__ int s[1024];
    int t = threadIdx.x;
    int base = t * 64;
    int sum = 0;
#pragma unroll 8
    for (int i = 0; i < 64; i++) sum += cnt[base + i];
    s[t] = sum;
    __syncthreads();
    for (int o = 1; o < 1024; o <<= 1) {
        int v = (t >= o) ? s[t - o] : 0;
        __syncthreads();
        s[t] += v;
        __syncthreads();
    }
    int run = s[t] - sum;
    for (int i = 0; i < 64; i++) { off[base + i] = run; run += cnt[base + i]; }
    if (t == 1023) off[EE] = run;
    if (which) {
        for (int i = t; i < EE; i += 1024)
            g_dis[i] = rsqrtf((float)(g_cnt_col[i] + 1));  // +1 self loop
    } else {
        if (t < NN) g_dinv[t] = g_dnode[t] > 0 ? 1.0f / (float)g_dnode[t] : 0.0f;
    }
}

// ---------------- pure CSR scatters ----------------
__global__ void k_scatter(const void* __restrict__ ei, const void* __restrict__ eei) {
    int is64 = g_is64;
    int stride = 1024 * blockDim.x;
    if (blockIdx.x < 1024) {
        for (int i = blockIdx.x * blockDim.x + threadIdx.x; i < NNZ; i += stride) {
            int src = ldidx(ei, i, is64);
            int he  = ldidx(ei, (long long)NNZ + i, is64);
            int pos = g_off_he[he] + atomicAdd(&g_cur_he[he], 1);
            g_members[pos] = src;
        }
    } else {
        int b = blockIdx.x - 1024;
        for (int j = b * blockDim.x + threadIdx.x; j < EENNZ; j += stride) {
            int row = ldidx(eei, j, is64);
            int col = ldidx(eei, (long long)EENNZ + j, is64);
            int pos = g_off_col[col] + atomicAdd(&g_cur_col[col], 1);
            g_rows[pos] = row;
        }
    }
}

// --- A accumulation: WARP per hyperedge (parallel pairs) + diag smem hist ----
__global__ void k_accA() {
    __shared__ float hd[NN];
    for (int i = threadIdx.x; i < NN; i += blockDim.x) hd[i] = 0.0f;
    __syncthreads();
    int w    = (blockIdx.x * blockDim.x + threadIdx.x) >> 5;
    int lane = threadIdx.x & 31;
    if (w < EE) {
        int s = g_off_he[w], e = g_off_he[w + 1];
        int k = e - s;
        if (k > 0) {
            float binv = 1.0f / (float)k;
            for (int p = lane; p < k; p += 32)
                atomicAdd(&hd[g_members[s + p]], binv);
            float* L = &g_small[OFF_T1];
            int tot = k * k;
            for (int p = lane; p < tot; p += 32) {
                int i = p / k, j = p - i * k;
                if (j > i) {
                    int mi = g_members[s + i], mj = g_members[s + j];
                    atomicAdd(&L[mi * 256 + mj], binv);
                }
            }
        }
    }
    __syncthreads();
    for (int i = threadIdx.x; i < NN; i += blockDim.x)
        if (hd[i] != 0.0f) atomicAdd(&g_small[OFF_A + i * 257], hd[i]);
}

// ---------------- 32x32 tile helper (k_prep + chain stages) ------------------
__device__ void tile_mm(const float* __restrict__ A, const float* __restrict__ B,
                        int lda, int ldb, int row0b, int col0b, int Kk,
                        float o[4], int tid) {
    __shared__ float As[16][34];
    __shared__ float Bs[16][34];
    int tx = tid & 15, ty = tid >> 4;
    float a00 = 0.f, a01 = 0.f, a10 = 0.f, a11 = 0.f;
    for (int kt = 0; kt < Kk; kt += 16) {
        int c = tid & 15, m = tid >> 4;
        As[c][m]      = A[(row0b + m) * lda + kt + c];
        As[c][m + 16] = A[(row0b + m + 16) * lda + kt + c];
        int n = tid & 31, r = tid >> 5;
        Bs[r][n]     = B[(kt + r) * ldb + col0b + n];
        Bs[r + 8][n] = B[(kt + r + 8) * ldb + col0b + n];
        __syncthreads();
#pragma unroll
        for (int kk = 0; kk < 16; kk++) {
            float2 a = *(const float2*)&As[kk][ty * 2];
            float2 b = *(const float2*)&Bs[kk][tx * 2];
            a00 += a.x * b.x; a01 += a.x * b.y;
            a10 += a.y * b.x; a11 += a.y * b.y;
        }
        __syncthreads();
    }
    o[0] = a00; o[1] = a01; o[2] = a10; o[3] = a11;
}

// --- prep: Wg2, WcHi/WcLo (fp16 hi/lo, packed k-pairs), biases ---------------
__global__ void k_prep(const float* __restrict__ Wg, const float* __restrict__ Wl2,
                       const float* __restrict__ Wl3, const float* __restrict__ Wo,
                       const float* __restrict__ bg, const float* __restrict__ bl2,
                       const float* __restrict__ bl3, const float* __restrict__ bo) {
    int b = blockIdx.x;
    int tid = threadIdx.x;
    int tx = tid & 15, ty = tid >> 4;
    if (b < 64) {
        float o[4];
        int r0 = (b >> 3) * 32, c0 = (b & 7) * 32;
        tile_mm(Wg, Wl2, 256, 256, r0, c0, 256, o, tid);
        int row = r0 + ty * 2, col = c0 + tx * 2;
        g_Wg2[row * 256 + col]           = o[0];
        g_Wg2[row * 256 + col + 1]       = o[1];
        g_Wg2[(row + 1) * 256 + col]     = o[2];
        g_Wg2[(row + 1) * 256 + col + 1] = o[3];
    } else if (b < 80) {
        int tb = b - 64;
        float o[4];
        int r0 = (tb >> 1) * 32, c0 = (tb & 1) * 32;
        tile_mm(Wl3, Wo, 128, 64, r0, c0, 128, o, tid);
        int row = r0 + ty * 2, col = c0 + tx * 2;   // row even: (row, row+1) = k-pair
        __half h0 = __float2half_rn(o[0]), h1 = __float2half_rn(o[2]);
        g_WcHi[(row >> 1) * 64 + col] = __halves2half2(h0, h1);
        g_WcLo[(row >> 1) * 64 + col] =
            __floats2half2_rn(o[0] - __half2float(h0), o[2] - __half2float(h1));
        __half h2 = __float2half_rn(o[1]), h3 = __float2half_rn(o[3]);
        g_WcHi[(row >> 1) * 64 + col + 1] = __halves2half2(h2, h3);
        g_WcLo[(row >> 1) * 64 + col + 1] =
            __floats2half2_rn(o[1] - __half2float(h2), o[3] - __half2float(h3));
    } else {
        int j = tid;
        float a = 0.0f;
        for (int k = 0; k < 256; k++) a += bg[k] * Wl2[k * 256 + j];
        g_b2[j] = a + bl2[j];
        if (j < 64) {
            float c = 0.0f;
            for (int k = 0; k < 128; k++) c += bl3[k] * Wo[k * 64 + j];
            g_bc[j] = c + bo[j];
        }
    }
}

// ------------- fused 5-GEMM chain + A symmetrize, 64 co-resident blocks ------
__device__ __forceinline__ void grid_bar(int k) {
    __syncthreads();
    __threadfence();
    if (threadIdx.x == 0) {
        int ticket = atomicAdd(&g_bar[k], 1);
        int target = (ticket / 64 + 1) * 64;
        while (*(volatile int*)&g_bar[k] < target) { }
    }
    __syncthreads();
    __threadfence();
}

__device__ void stage_gemm(const float* __restrict__ A, const float* __restrict__ B,
                           float* __restrict__ C, __half* __restrict__ Ch,
                           const float* __restrict__ bias,
                           const float* __restrict__ rowscale,
                           int act, int transA) {
    float o[4];
    int tid = threadIdx.x;
    int tx = tid & 15, ty = tid >> 4;
    int by = blockIdx.x >> 3, bx = blockIdx.x & 7;
    if (transA) {
        __shared__ float As[16][34];
        __shared__ float Bs[16][34];
        float a00 = 0.f, a01 = 0.f, a10 = 0.f, a11 = 0.f;
        for (int kt = 0; kt < 256; kt += 16) {
            int m = tid & 31, c = tid >> 5;
            As[c][m]     = A[(kt + c) * 256 + by * 32 + m];
            As[c + 8][m] = A[(kt + c + 8) * 256 + by * 32 + m];
            int n = tid & 31, r = tid >> 5;
            Bs[r][n]     = B[(kt + r) * 256 + bx * 32 + n];
            Bs[r + 8][n] = B[(kt + r + 8) * 256 + bx * 32 + n];
            __syncthreads();
#pragma unroll
            for (int kk = 0; kk < 16; kk++) {
                float2 a = *(const float2*)&As[kk][ty * 2];
                float2 b = *(const float2*)&Bs[kk][tx * 2];
                a00 += a.x * b.x; a01 += a.x * b.y;
                a10 += a.y * b.x; a11 += a.y * b.y;
            }
            __syncthreads();
        }
        o[0] = a00; o[1] = a01; o[2] = a10; o[3] = a11;
    } else {
        tile_mm(A, B, 256, 256, by * 32, bx * 32, 256, o, tid);
    }
    int row = by * 32 + ty * 2, col = bx * 32 + tx * 2;
    float r0 = rowscale ? rowscale[row]     : 1.0f;
    float r1 = rowscale ? rowscale[row + 1] : 1.0f;
    float b0 = bias ? bias[col]     : 0.0f;
    float b1 = bias ? bias[col + 1] : 0.0f;
    float o00 = o[0] * r0 + b0, o01 = o[1] * r0 + b1;
    float o10 = o[2] * r1 + b0, o11 = o[3] * r1 + b1;
    if (act) { o00 = lrelu(o00); o01 = lrelu(o01); o10 = lrelu(o10); o11 = lrelu(o11); }
    if (Ch) {
        *(__half2*)&Ch[row * 256 + col]       = __floats2half2_rn(o00, o01);
        *(__half2*)&Ch[(row + 1) * 256 + col] = __floats2half2_rn(o10, o11);
    } else {
        C[row * 256 + col]           = o00;
        C[row * 256 + col + 1]       = o01;
        C[(row + 1) * 256 + col]     = o10;
        C[(row + 1) * 256 + col + 1] = o11;
    }
}

__global__ __launch_bounds__(256) void k_chain(const float* __restrict__ ne,
                                               const float* __restrict__ W_hg,
                                               const float* __restrict__ b_hg,
                                               const float* __restrict__ W_lin,
                                               const float* __restrict__ b_lin) {
    float* A  = &g_small[OFF_A];
    float* x  = &g_small[OFF_X];
    float* y  = &g_small[OFF_Y];
    float* G  = &g_small[OFF_G];
    float* y2 = &g_small[OFF_Y2];
    // A = L + L^T (each block does 4 rows) — consumed after grid_bar(0)
    {
        const float* L = &g_small[OFF_T1];
        int j = threadIdx.x;
#pragma unroll
        for (int r = 0; r < 4; r++) {
            int i = blockIdx.x * 4 + r;
            if (j > i) {
                float sv = L[i * 256 + j] + L[j * 256 + i];
                A[i * 256 + j] = sv;
                A[j * 256 + i] = sv;
            } else if (j == i) {
                A[i * 257] += 2.0f * L[i * 257];
            }
        }
    }
    stage_gemm(ne, W_hg, x, nullptr, nullptr, nullptr, 0, 0);        // x = ne @ W_hg
    grid_bar(0);
    stage_gemm(A, x, y, nullptr, b_hg, g_dinv, 1, 0);                // y = lrelu(dinv*(A@x)+b)
    grid_bar(1);
    stage_gemm(y, y, G, nullptr, nullptr, nullptr, 0, 1);            // G = y^T @ y
    grid_bar(2);
    stage_gemm(G, W_lin, y2, nullptr, b_lin, nullptr, 1, 0);         // y2 = lrelu(G@W_lin+b)
    grid_bar(3);
    stage_gemm(y2, g_Wg2, nullptr, g_T16, nullptr, nullptr, 0, 0);   // T16 = y2 @ Wg2
}

// ------ w[e] = dis[e] * mean_{members} T16[src]  (warp per row, 16B LDG) -----
__global__ void k_u() {
    int e    = blockIdx.x * 8 + (threadIdx.x >> 5);
    int lane = threadIdx.x & 31;
    int s = g_off_he[e], en = g_off_he[e + 1];
    const __half* __restrict__ T = g_T16;
    float acc[8];
#pragma unroll
    for (int q = 0; q < 8; q++) acc[q] = 0.0f;
    int m = s;
    for (; m + 4 <= en; m += 4) {
        int idx[4];
#pragma unroll
        for (int q = 0; q < 4; q++) idx[q] = g_members[m + q];
        uint4 v[4];
#pragma unroll
        for (int q = 0; q < 4; q++)
            v[q] = *(const uint4*)&T[idx[q] * 256 + lane * 8];
#pragma unroll
        for (int q = 0; q < 4; q++) acc_half8(acc, v[q]);
    }
    for (; m < en; m++) {
        uint4 v = *(const uint4*)&T[g_members[m] * 256 + lane * 8];
        acc_half8(acc, v);
    }
    int k = en - s;
    float sc = (k > 0 ? 1.0f / (float)k : 0.0f) * g_dis[e];
    union { uint4 u; __half2 h[4]; } po;
#pragma unroll
    for (int r = 0; r < 4; r++)
        po.h[r] = __floats2half2_rn(acc[2 * r] * sc, acc[2 * r + 1] * sc);
    *(uint4*)&g_w[(size_t)e * 256 + lane * 8] = po.u;
}

// --- GCN agg (warp per row, 16B fp16 LDG, MLP-8) + bias + leaky, fp16 out ----
__global__ void k_agg() {
    int c    = blockIdx.x * 8 + (threadIdx.x >> 5);
    int lane = threadIdx.x & 31;
    float acc[8];
    {   // self loop
        uint4 v = *(const uint4*)&g_w[(size_t)c * 256 + lane * 8];
        union { uint4 u; __half2 h[4]; } pk;
        pk.u = v;
#pragma unroll
        for (int r = 0; r < 4; r++) {
            float2 f = __half22float2(pk.h[r]);
            acc[2 * r] = f.x; acc[2 * r + 1] = f.y;
        }
    }
    int s = g_off_col[c], en = g_off_col[c + 1];
    int j = s;
    for (; j + 8 <= en; j += 8) {
        int idx[8];
#pragma unroll
        for (int q = 0; q < 8; q++) idx[q] = g_rows[j + q];
        uint4 v[8];
#pragma unroll
        for (int q = 0; q < 8; q++)
            v[q] = *(const uint4*)&g_w[(size_t)idx[q] * 256 + lane * 8];
#pragma unroll
        for (int q = 0; q < 8; q++) acc_half8(acc, v[q]);
    }
    for (; j < en; j++) {
        uint4 v = *(const uint4*)&g_w[(size_t)g_rows[j] * 256 + lane * 8];
        acc_half8(acc, v);
    }
    float dc = g_dis[c];
    float4 b0 = *(const float4*)&g_b2[lane * 8];
    float4 b1 = *(const float4*)&g_b2[lane * 8 + 4];
    float bb[8] = {b0.x, b0.y, b0.z, b0.w, b1.x, b1.y, b1.z, b1.w};
    union { uint4 u; __half2 h[4]; } po;
#pragma unroll
    for (int r = 0; r < 4; r++)
        po.h[r] = __floats2half2_rn(lrelu(dc * acc[2 * r] + bb[2 * r]),
                                    lrelu(dc * acc[2 * r + 1] + bb[2 * r + 1]));
    *(uint4*)&g_v[(size_t)c * 256 + lane * 8] = po.u;
}

// ------- motif: min(3 fp16 rows) -> fp16 MMA (Wc hi/lo 2-pass) ---------------
#define SMH_STRIDE 264
__global__ __launch_bounds__(256, 5) void k_motif(const void* __restrict__ mei,
                                                  float* __restrict__ out) {
    extern __shared__ __half smh[];    // [32][SMH_STRIDE] fp16 min values
    __shared__ int sIdx[96];
    int tid = threadIdx.x, lane = tid & 31, wid = tid >> 5;
    int is64 = g_is64;
    int mbase = blockIdx.x * 32;
    if (tid < 96) sIdx[tid] = ldidx(mei, 3LL * mbase + tid, is64);
    __syncthreads();
    // stage 1: min of 3 fp16 rows -> fp16 smem (exact, __hmin2)
#pragma unroll
    for (int mm = wid * 4; mm < wid * 4 + 4; mm++) {
        const __half* __restrict__ r0 = &g_v[(size_t)sIdx[3 * mm]     * 256];
        const __half* __restrict__ r1 = &g_v[(size_t)sIdx[3 * mm + 1] * 256];
        const __half* __restrict__ r2 = &g_v[(size_t)sIdx[3 * mm + 2] * 256];
        union { uint4 u; __half2 h[4]; } A, B, C, O;
        A.u = *(const uint4*)&r0[lane * 8];
        B.u = *(const uint4*)&r1[lane * 8];
        C.u = *(const uint4*)&r2[lane * 8];
#pragma unroll
        for (int q = 0; q < 4; q++)
            O.h[q] = __hmin2(__hmin2(A.h[q], B.h[q]), C.h[q]);
        *(uint4*)&smh[mm * SMH_STRIDE + lane * 8] = O.u;
    }
    __syncthreads();
    // stage 2: [32 x 256] @ [256 x 64] via m16n8k16 f16, hi+lo passes
    int wm = wid >> 2, wn = wid & 3;
    int gid = lane >> 2, tig = lane & 3;
    float acc[2][4];
#pragma unroll
    for (int nt = 0; nt < 2; nt++)
#pragma unroll
        for (int q = 0; q < 4; q++) acc[nt][q] = 0.0f;
    const __half2* __restrict__ Whi = g_WcHi;
    const __half2* __restrict__ Wlo = g_WcLo;
    int mr = wm * 16 + gid;
    for (int k0 = 0; k0 < 256; k0 += 16) {
        unsigned a0 = *(const unsigned*)&smh[mr * SMH_STRIDE + k0 + 2 * tig];
        unsigned a1 = *(const unsigned*)&smh[(mr + 8) * SMH_STRIDE + k0 + 2 * tig];
        unsigned a2 = *(const unsigned*)&smh[mr * SMH_STRIDE + k0 + 8 + 2 * tig];
        unsigned a3 = *(const unsigned*)&smh[(mr + 8) * SMH_STRIDE + k0 + 8 + 2 * tig];
        int kb = (k0 >> 1) + tig;
#pragma unroll
        for (int nt = 0; nt < 2; nt++) {
            int n = wn * 16 + nt * 8 + gid;
            unsigned bh0 = *(const unsigned*)&Whi[kb * 64 + n];
            unsigned bh1 = *(const unsigned*)&Whi[(kb + 4) * 64 + n];
            unsigned bl0 = *(const unsigned*)&Wlo[kb * 64 + n];
            unsigned bl1 = *(const unsigned*)&Wlo[(kb + 4) * 64 + n];
            mma_f16(acc[nt], a0, a1, a2, a3, bh0, bh1);
            mma_f16(acc[nt], a0, a1, a2, a3, bl0, bl1);
        }
    }
    // epilogue
    int ra = mbase + wm * 16 + gid;
    int rb = ra + 8;
#pragma unroll
    for (int nt = 0; nt < 2; nt++) {
        int col = wn * 16 + nt * 8 + tig * 2;
        float b0 = g_bc[col], b1 = g_bc[col + 1];
        float* d = acc[nt];
        *(float2*)&out[(size_t)ra * 64 + col] = make_float2(d[0] + b0, d[1] + b1);
        *(float2*)&out[(size_t)rb * 64 + col] = make_float2(d[2] + b0, d[3] + b1);
    }
}

// ---------------- host ----------------
extern "C" void kernel_launch(void* const* d_in, const int* in_sizes, int n_in,
                              void* d_out, int out_size) {
    const float* node_embeds = (const float*)d_in[0];
    const float* W_hg   = (const float*)d_in[1];
    const float* b_hg   = (const float*)d_in[2];
    const float* W_lin  = (const float*)d_in[3];
    const float* b_lin  = (const float*)d_in[4];
    const float* W_gcn  = (const float*)d_in[5];
    const float* b_gcn  = (const float*)d_in[6];
    const float* W_lin2 = (const float*)d_in[7];
    const float* b_lin2 = (const float*)d_in[8];
    const float* W_lin3 = (const float*)d_in[9];
    const float* b_lin3 = (const float*)d_in[10];
    const float* W_out  = (const float*)d_in[11];
    const float* b_out  = (const float*)d_in[12];
    const void*  ei     = d_in[13];
    const void*  eei    = d_in[14];
    const void*  mei    = d_in[15];
    float* out = (float*)d_out;

    k_initdet<<<256, 256>>>((const unsigned*)ei);
    k_hist<<<2048, 256>>>(ei, eei);
    k_scan<<<2, 1024>>>();
    k_agg<<<8192, 256>>>();            // DIAGNOSTIC full-size (profiled slot 4);
                                       // inputs steady-state/zero, g_v overwritten below
    k_scatter<<<2048, 256>>>(ei, eei);
    k_accA<<<8192, 256>>>();
    k_prep<<<81, 256>>>(W_gcn, W_lin2, W_lin3, W_out, b_gcn, b_lin2, b_lin3, b_out);
    k_chain<<<64, 256>>>(node_embeds, W_hg, b_hg, W_lin, b_lin);

    k_u<<<8192, 256>>>();
    k_agg<<<8192, 256>>>();
    k_motif<<<2048, 256, 32 * SMH_STRIDE * 2>>>(mei, out);
}

// round 15
// speedup vs baseline: 1.4148x; 1.4148x over previous
#include <cuda_runtime.h>
#include <cuda_fp16.h>
#include <cstdint>

#define NN      256
#define EE      65536
#define MMOT    65536
#define NNZ     524288
#define EENNZ   524288
#define SLOPE   0.01f

// ---------------- device scratch (static, no allocations) ----------------
__device__ int   g_is64;
__device__ int   g_bar[8];             // monotonic grid-barrier counters
__device__ float g_small[7 * 65536];   // A, x, y, G, y2, T1(L scratch), spare
#define OFF_A   0
#define OFF_X   (1 * 65536)
#define OFF_Y   (2 * 65536)
#define OFF_G   (3 * 65536)
#define OFF_Y2  (4 * 65536)
#define OFF_T1  (5 * 65536)
__device__ float   g_Wg2[65536];        // W_gcn @ W_lin2
__device__ __half2 g_WcHi[128 * 64];    // fp16 hi of Wc, packed (k,k+1) pairs
__device__ __half2 g_WcLo[128 * 64];    // fp16 lo residual, same packing
__device__ __half  g_T16[65536];        // fp16 T = y2 @ Wg2
__device__ float   g_b2[256];
__device__ float   g_bc[64];
__device__ float   g_dinv[256];
__device__ float   g_dis[EE];
__device__ int     g_cnt_he[EE];
__device__ int     g_cnt_col[EE];
__device__ int     g_off_he[EE + 4];
__device__ int     g_off_col[EE + 4];
__device__ int     g_cur_he[EE];
__device__ int     g_cur_col[EE];
__device__ int     g_dnode[NN];
__device__ int     g_members[NNZ];
__device__ int     g_rows[EENNZ];
__device__ __half  g_w[(size_t)EE * 256];  // dis[e] * mean-agg rows (fp16, 32 MB)
__device__ __half  g_v[(size_t)EE * 256];  // GCN+lin2 output per hyperedge (fp16, 32 MB)

__device__ __forceinline__ int ldidx(const void* p, long long i, int is64) {
    return is64 ? (int)((const long long*)p)[i] : ((const int*)p)[i];
}
__device__ __forceinline__ float lrelu(float x) { return x >= 0.0f ? x : SLOPE * x; }
__device__ __forceinline__ void mma_f16(float* d,
                                        unsigned a0, unsigned a1, unsigned a2, unsigned a3,
                                        unsigned b0, unsigned b1) {
    asm volatile(
        "mma.sync.aligned.m16n8k16.row.col.f32.f16.f16.f32 "
        "{%0,%1,%2,%3},{%4,%5,%6,%7},{%8,%9},{%0,%1,%2,%3};"
        : "+f"(d[0]), "+f"(d[1]), "+f"(d[2]), "+f"(d[3])
        : "r"(a0), "r"(a1), "r"(a2), "r"(a3), "r"(b0), "r"(b1));
}
// accumulate a 16B fp16 chunk into 8 fp32 accumulators
__device__ __forceinline__ void acc_half8(float* acc, uint4 raw) {
    union { uint4 u; __half2 h[4]; } pk;
    pk.u = raw;
#pragma unroll
    for (int r = 0; r < 4; r++) {
        float2 f = __half22float2(pk.h[r]);
        acc[2 * r]     += f.x;
        acc[2 * r + 1] += f.y;
    }
}

// ---------------- init + index dtype detection (fused) ----------------
__global__ void k_initdet(const unsigned* __restrict__ p) {
    int stride = gridDim.x * blockDim.x;
    for (int t = blockIdx.x * blockDim.x + threadIdx.x; t < EE; t += stride) {
        g_small[OFF_A + t]  = 0.0f;
        g_small[OFF_T1 + t] = 0.0f;
        g_cnt_he[t] = 0; g_cnt_col[t] = 0;
        g_cur_he[t] = 0; g_cur_col[t] = 0;
        if (t < NN) g_dnode[t] = 0;
    }
    if (blockIdx.x == 0) {
        __shared__ int nz;
        if (threadIdx.x == 0) nz = 0;
        __syncthreads();
        int any = 0;
        for (int i = threadIdx.x; i < 4096; i += blockDim.x)
            any |= (p[2 * i + 1] != 0u);
        if (any) atomicOr(&nz, 1);
        __syncthreads();
        if (threadIdx.x == 0) g_is64 = nz ? 0 : 1;
    }
}

// ---------------- fused histograms ----------------
__global__ void k_hist(const void* __restrict__ ei, const void* __restrict__ eei) {
    int is64 = g_is64;
    __shared__ int h[NN];
    if (blockIdx.x < 1024) {
        for (int i = threadIdx.x; i < NN; i += blockDim.x) h[i] = 0;
        __syncthreads();
        int stride = 1024 * blockDim.x;
        for (int i = blockIdx.x * blockDim.x + threadIdx.x; i < NNZ; i += stride) {
            int src = ldidx(ei, i, is64);
            int he  = ldidx(ei, (long long)NNZ + i, is64);
            atomicAdd(&g_cnt_he[he], 1);
            atomicAdd(&h[src], 1);
        }
        __syncthreads();
        for (int i = threadIdx.x; i < NN; i += blockDim.x)
            if (h[i]) atomicAdd(&g_dnode[i], h[i]);
    } else {
        int b = blockIdx.x - 1024;
        int stride = 1024 * blockDim.x;
        for (int j = b * blockDim.x + threadIdx.x; j < EENNZ; j += stride) {
            int col = ldidx(eei, (long long)EENNZ + j, is64);
            atomicAdd(&g_cnt_col[col], 1);
        }
    }
}

// ------- 64K-bin exclusive scan, int4 I/O (2 blocks) + degree prep ----------
__global__ void k_scan() {
    int which = blockIdx.x;
    const int4* cnt4 = (const int4*)(which ? g_cnt_col : g_cnt_he);
    int*        off  = which ? g_off_col : g_off_he;
    int4*       off4 = (int4*)off;
    __shared__ int s[1024];
    int t = threadIdx.x;
    int sum = 0;
#pragma unroll
    for (int i = 0; i < 16; i++) {
        int4 c = cnt4[t * 16 + i];
        sum += c.x + c.y + c.z + c.w;
    }
    s[t] = sum;
    __syncthreads();
    for (int o = 1; o < 1024; o <<= 1) {
        int v = (t >= o) ? s[t - o] : 0;
        __syncthreads();
        s[t] += v;
        __syncthreads();
    }
    int run = s[t] - sum;   // exclusive prefix of this thread's 64-bin chunk
#pragma unroll
    for (int i = 0; i < 16; i++) {
        int4 c = cnt4[t * 16 + i];   // L1 hit
        int4 o;
        o.x = run; run += c.x;
        o.y = run; run += c.y;
        o.z = run; run += c.z;
        o.w = run; run += c.w;
        off4[t * 16 + i] = o;
    }
    if (t == 1023) off[EE] = run;
    if (which) {
        for (int i = t; i < EE; i += 1024)
            g_dis[i] = rsqrtf((float)(g_cnt_col[i] + 1));  // +1 self loop
    } else {
        if (t < NN) g_dinv[t] = g_dnode[t] > 0 ? 1.0f / (float)g_dnode[t] : 0.0f;
    }
}

// ---------------- pure CSR scatters ----------------
__global__ void k_scatter(const void* __restrict__ ei, const void* __restrict__ eei) {
    int is64 = g_is64;
    int stride = 1024 * blockDim.x;
    if (blockIdx.x < 1024) {
        for (int i = blockIdx.x * blockDim.x + threadIdx.x; i < NNZ; i += stride) {
            int src = ldidx(ei, i, is64);
            int he  = ldidx(ei, (long long)NNZ + i, is64);
            int pos = g_off_he[he] + atomicAdd(&g_cur_he[he], 1);
            g_members[pos] = src;
        }
    } else {
        int b = blockIdx.x - 1024;
        for (int j = b * blockDim.x + threadIdx.x; j < EENNZ; j += stride) {
            int row = ldidx(eei, j, is64);
            int col = ldidx(eei, (long long)EENNZ + j, is64);
            int pos = g_off_col[col] + atomicAdd(&g_cur_col[col], 1);
            g_rows[pos] = row;
        }
    }
}

// --- A accumulation: WARP per hyperedge (parallel pairs) + diag smem hist ----
__global__ void k_accA() {
    __shared__ float hd[NN];
    for (int i = threadIdx.x; i < NN; i += blockDim.x) hd[i] = 0.0f;
    __syncthreads();
    int w    = (blockIdx.x * blockDim.x + threadIdx.x) >> 5;
    int lane = threadIdx.x & 31;
    if (w < EE) {
        int s = g_off_he[w], e = g_off_he[w + 1];
        int k = e - s;
        if (k > 0) {
            float binv = 1.0f / (float)k;
            for (int p = lane; p < k; p += 32)
                atomicAdd(&hd[g_members[s + p]], binv);
            float* L = &g_small[OFF_T1];
            int tot = k * k;
            for (int p = lane; p < tot; p += 32) {
                int i = p / k, j = p - i * k;
                if (j > i) {
                    int mi = g_members[s + i], mj = g_members[s + j];
                    atomicAdd(&L[mi * 256 + mj], binv);
                }
            }
        }
    }
    __syncthreads();
    for (int i = threadIdx.x; i < NN; i += blockDim.x)
        if (hd[i] != 0.0f) atomicAdd(&g_small[OFF_A + i * 257], hd[i]);
}

// ---------------- 32x32 tile helper (k_prep) ---------------------------------
__device__ void tile_mm(const float* __restrict__ A, const float* __restrict__ B,
                        int lda, int ldb, int row0b, int col0b, int Kk,
                        float o[4], int tid) {
    __shared__ float As[16][34];
    __shared__ float Bs[16][34];
    int tx = tid & 15, ty = tid >> 4;
    float a00 = 0.f, a01 = 0.f, a10 = 0.f, a11 = 0.f;
    for (int kt = 0; kt < Kk; kt += 16) {
        int c = tid & 15, m = tid >> 4;
        As[c][m]      = A[(row0b + m) * lda + kt + c];
        As[c][m + 16] = A[(row0b + m + 16) * lda + kt + c];
        int n = tid & 31, r = tid >> 5;
        Bs[r][n]     = B[(kt + r) * ldb + col0b + n];
        Bs[r + 8][n] = B[(kt + r + 8) * ldb + col0b + n];
        __syncthreads();
#pragma unroll
        for (int kk = 0; kk < 16; kk++) {
            float2 a = *(const float2*)&As[kk][ty * 2];
            float2 b = *(const float2*)&Bs[kk][tx * 2];
            a00 += a.x * b.x; a01 += a.x * b.y;
            a10 += a.y * b.x; a11 += a.y * b.y;
        }
        __syncthreads();
    }
    o[0] = a00; o[1] = a01; o[2] = a10; o[3] = a11;
}

// --- prep: Wg2, WcHi/WcLo (fp16 hi/lo, packed k-pairs), biases ---------------
__global__ void k_prep(const float* __restrict__ Wg, const float* __restrict__ Wl2,
                       const float* __restrict__ Wl3, const float* __restrict__ Wo,
                       const float* __restrict__ bg, const float* __restrict__ bl2,
                       const float* __restrict__ bl3, const float* __restrict__ bo) {
    int b = blockIdx.x;
    int tid = threadIdx.x;
    int tx = tid & 15, ty = tid >> 4;
    if (b < 64) {
        float o[4];
        int r0 = (b >> 3) * 32, c0 = (b & 7) * 32;
        tile_mm(Wg, Wl2, 256, 256, r0, c0, 256, o, tid);
        int row = r0 + ty * 2, col = c0 + tx * 2;
        g_Wg2[row * 256 + col]           = o[0];
        g_Wg2[row * 256 + col + 1]       = o[1];
        g_Wg2[(row + 1) * 256 + col]     = o[2];
        g_Wg2[(row + 1) * 256 + col + 1] = o[3];
    } else if (b < 80) {
        int tb = b - 64;
        float o[4];
        int r0 = (tb >> 1) * 32, c0 = (tb & 1) * 32;
        tile_mm(Wl3, Wo, 128, 64, r0, c0, 128, o, tid);
        int row = r0 + ty * 2, col = c0 + tx * 2;   // row even: (row, row+1) = k-pair
        __half h0 = __float2half_rn(o[0]), h1 = __float2half_rn(o[2]);
        g_WcHi[(row >> 1) * 64 + col] = __halves2half2(h0, h1);
        g_WcLo[(row >> 1) * 64 + col] =
            __floats2half2_rn(o[0] - __half2float(h0), o[2] - __half2float(h1));
        __half h2 = __float2half_rn(o[1]), h3 = __float2half_rn(o[3]);
        g_WcHi[(row >> 1) * 64 + col + 1] = __halves2half2(h2, h3);
        g_WcLo[(row >> 1) * 64 + col + 1] =
            __floats2half2_rn(o[1] - __half2float(h2), o[3] - __half2float(h3));
    } else {
        int j = tid;
        float a = 0.0f;
        for (int k = 0; k < 256; k++) a += bg[k] * Wl2[k * 256 + j];
        g_b2[j] = a + bl2[j];
        if (j < 64) {
            float c = 0.0f;
            for (int k = 0; k < 128; k++) c += bl3[k] * Wo[k * 64 + j];
            g_bc[j] = c + bo[j];
        }
    }
}

// ------ fused 5-GEMM chain + A symmetrize, 256 co-resident blocks ------------
__device__ __forceinline__ void grid_bar(int k) {
    __syncthreads();
    __threadfence();
    if (threadIdx.x == 0) {
        int ticket = atomicAdd(&g_bar[k], 1);
        int target = (ticket / 256 + 1) * 256;
        while (*(volatile int*)&g_bar[k] < target) { }
    }
    __syncthreads();
    __threadfence();
}

// 16x16 tile, one output per thread (256 blocks cover 256x256)
__device__ void stage_gemm(const float* __restrict__ A, const float* __restrict__ B,
                           float* __restrict__ C, __half* __restrict__ Ch,
                           const float* __restrict__ bias,
                           const float* __restrict__ rowscale,
                           int act, int transA) {
    __shared__ float As[16][17];
    __shared__ float Bs[16][17];
    int tid = threadIdx.x;
    int tx = tid & 15, ty = tid >> 4;
    int by = blockIdx.x >> 4, bx = blockIdx.x & 15;
    int row = by * 16 + ty;
    int col = bx * 16 + tx;
    float acc = 0.0f;
    for (int kt = 0; kt < 256; kt += 16) {
        As[ty][tx] = transA ? A[(kt + tx) * 256 + row] : A[row * 256 + kt + tx];
        Bs[ty][tx] = B[(kt + ty) * 256 + col];
        __syncthreads();
#pragma unroll
        for (int kk = 0; kk < 16; kk++) acc += As[ty][kk] * Bs[kk][tx];
        __syncthreads();
    }
    if (rowscale) acc *= rowscale[row];
    if (bias)     acc += bias[col];
    if (act)      acc = lrelu(acc);
    if (Ch) Ch[row * 256 + col] = __float2half_rn(acc);
    else    C[row * 256 + col]  = acc;
}

__global__ __launch_bounds__(256) void k_chain(const float* __restrict__ ne,
                                               const float* __restrict__ W_hg,
                                               const float* __restrict__ b_hg,
                                               const float* __restrict__ W_lin,
                                               const float* __restrict__ b_lin) {
    float* A  = &g_small[OFF_A];
    float* x  = &g_small[OFF_X];
    float* y  = &g_small[OFF_Y];
    float* G  = &g_small[OFF_G];
    float* y2 = &g_small[OFF_Y2];
    // A = L + L^T (each block does 1 row) — consumed after grid_bar(0)
    {
        const float* L = &g_small[OFF_T1];
        int i = blockIdx.x, j = threadIdx.x;
        if (j > i) {
            float sv = L[i * 256 + j] + L[j * 256 + i];
            A[i * 256 + j] = sv;
            A[j * 256 + i] = sv;
        } else if (j == i) {
            A[i * 257] += 2.0f * L[i * 257];
        }
    }
    stage_gemm(ne, W_hg, x, nullptr, nullptr, nullptr, 0, 0);        // x = ne @ W_hg
    grid_bar(0);
    stage_gemm(A, x, y, nullptr, b_hg, g_dinv, 1, 0);                // y = lrelu(dinv*(A@x)+b)
    grid_bar(1);
    stage_gemm(y, y, G, nullptr, nullptr, nullptr, 0, 1);            // G = y^T @ y
    grid_bar(2);
    stage_gemm(G, W_lin, y2, nullptr, b_lin, nullptr, 1, 0);         // y2 = lrelu(G@W_lin+b)
    grid_bar(3);
    stage_gemm(y2, g_Wg2, nullptr, g_T16, nullptr, nullptr, 0, 0);   // T16 = y2 @ Wg2
}

// ------ w[e] = dis[e] * mean_{members} T16[src]  (warp per row, 16B LDG) -----
__global__ void k_u() {
    int e    = blockIdx.x * 8 + (threadIdx.x >> 5);
    int lane = threadIdx.x & 31;
    int s = g_off_he[e], en = g_off_he[e + 1];
    const __half* __restrict__ T = g_T16;
    float acc[8];
#pragma unroll
    for (int q = 0; q < 8; q++) acc[q] = 0.0f;
    int m = s;
    for (; m + 4 <= en; m += 4) {
        int idx[4];
#pragma unroll
        for (int q = 0; q < 4; q++) idx[q] = g_members[m + q];
        uint4 v[4];
#pragma unroll
        for (int q = 0; q < 4; q++)
            v[q] = *(const uint4*)&T[idx[q] * 256 + lane * 8];
#pragma unroll
        for (int q = 0; q < 4; q++) acc_half8(acc, v[q]);
    }
    for (; m < en; m++) {
        uint4 v = *(const uint4*)&T[g_members[m] * 256 + lane * 8];
        acc_half8(acc, v);
    }
    int k = en - s;
    float sc = (k > 0 ? 1.0f / (float)k : 0.0f) * g_dis[e];
    union { uint4 u; __half2 h[4]; } po;
#pragma unroll
    for (int r = 0; r < 4; r++)
        po.h[r] = __floats2half2_rn(acc[2 * r] * sc, acc[2 * r + 1] * sc);
    *(uint4*)&g_w[(size_t)e * 256 + lane * 8] = po.u;
}

// --- GCN agg (warp per row, 16B fp16 LDG, MLP-8) + bias + leaky, fp16 out ----
__global__ void k_agg() {
    int c    = blockIdx.x * 8 + (threadIdx.x >> 5);
    int lane = threadIdx.x & 31;
    float acc[8];
    {   // self loop
        uint4 v = *(const uint4*)&g_w[(size_t)c * 256 + lane * 8];
        union { uint4 u; __half2 h[4]; } pk;
        pk.u = v;
#pragma unroll
        for (int r = 0; r < 4; r++) {
            float2 f = __half22float2(pk.h[r]);
            acc[2 * r] = f.x; acc[2 * r + 1] = f.y;
        }
    }
    int s = g_off_col[c], en = g_off_col[c + 1];
    int j = s;
    for (; j + 8 <= en; j += 8) {
        int idx[8];
#pragma unroll
        for (int q = 0; q < 8; q++) idx[q] = g_rows[j + q];
        uint4 v[8];
#pragma unroll
        for (int q = 0; q < 8; q++)
            v[q] = *(const uint4*)&g_w[(size_t)idx[q] * 256 + lane * 8];
#pragma unroll
        for (int q = 0; q < 8; q++) acc_half8(acc, v[q]);
    }
    for (; j < en; j++) {
        uint4 v = *(const uint4*)&g_w[(size_t)g_rows[j] * 256 + lane * 8];
        acc_half8(acc, v);
    }
    float dc = g_dis[c];
    float4 b0 = *(const float4*)&g_b2[lane * 8];
    float4 b1 = *(const float4*)&g_b2[lane * 8 + 4];
    float bb[8] = {b0.x, b0.y, b0.z, b0.w, b1.x, b1.y, b1.z, b1.w};
    union { uint4 u; __half2 h[4]; } po;
#pragma unroll
    for (int r = 0; r < 4; r++)
        po.h[r] = __floats2half2_rn(lrelu(dc * acc[2 * r] + bb[2 * r]),
                                    lrelu(dc * acc[2 * r + 1] + bb[2 * r + 1]));
    *(uint4*)&g_v[(size_t)c * 256 + lane * 8] = po.u;
}

// ------- motif: min(3 fp16 rows) -> fp16 MMA (Wc hi/lo 2-pass) ---------------
#define SMH_STRIDE 264
__global__ __launch_bounds__(256, 5) void k_motif(const void* __restrict__ mei,
                                                  float* __restrict__ out) {
    extern __shared__ __half smh[];    // [32][SMH_STRIDE] fp16 min values
    __shared__ int sIdx[96];
    int tid = threadIdx.x, lane = tid & 31, wid = tid >> 5;
    int is64 = g_is64;
    int mbase = blockIdx.x * 32;
    if (tid < 96) sIdx[tid] = ldidx(mei, 3LL * mbase + tid, is64);
    __syncthreads();
    // stage 1: min of 3 fp16 rows -> fp16 smem (exact, __hmin2)
#pragma unroll
    for (int mm = wid * 4; mm < wid * 4 + 4; mm++) {
        const __half* __restrict__ r0 = &g_v[(size_t)sIdx[3 * mm]     * 256];
        const __half* __restrict__ r1 = &g_v[(size_t)sIdx[3 * mm + 1] * 256];
        const __half* __restrict__ r2 = &g_v[(size_t)sIdx[3 * mm + 2] * 256];
        union { uint4 u; __half2 h[4]; } A, B, C, O;
        A.u = *(const uint4*)&r0[lane * 8];
        B.u = *(const uint4*)&r1[lane * 8];
        C.u = *(const uint4*)&r2[lane * 8];
#pragma unroll
        for (int q = 0; q < 4; q++)
            O.h[q] = __hmin2(__hmin2(A.h[q], B.h[q]), C.h[q]);
        *(uint4*)&smh[mm * SMH_STRIDE + lane * 8] = O.u;
    }
    __syncthreads();
    // stage 2: [32 x 256] @ [256 x 64] via m16n8k16 f16, hi+lo passes
    int wm = wid >> 2, wn = wid & 3;
    int gid = lane >> 2, tig = lane & 3;
    float acc[2][4];
#pragma unroll
    for (int nt = 0; nt < 2; nt++)
#pragma unroll
        for (int q = 0; q < 4; q++) acc[nt][q] = 0.0f;
    const __half2* __restrict__ Whi = g_WcHi;
    const __half2* __restrict__ Wlo = g_WcLo;
    int mr = wm * 16 + gid;
    for (int k0 = 0; k0 < 256; k0 += 16) {
        unsigned a0 = *(const unsigned*)&smh[mr * SMH_STRIDE + k0 + 2 * tig];
        unsigned a1 = *(const unsigned*)&smh[(mr + 8) * SMH_STRIDE + k0 + 2 * tig];
        unsigned a2 = *(const unsigned*)&smh[mr * SMH_STRIDE + k0 + 8 + 2 * tig];
        unsigned a3 = *(const unsigned*)&smh[(mr + 8) * SMH_STRIDE + k0 + 8 + 2 * tig];
        int kb = (k0 >> 1) + tig;
#pragma unroll
        for (int nt = 0; nt < 2; nt++) {
            int n = wn * 16 + nt * 8 + gid;
            unsigned bh0 = *(const unsigned*)&Whi[kb * 64 + n];
            unsigned bh1 = *(const unsigned*)&Whi[(kb + 4) * 64 + n];
            unsigned bl0 = *(const unsigned*)&Wlo[kb * 64 + n];
            unsigned bl1 = *(const unsigned*)&Wlo[(kb + 4) * 64 + n];
            mma_f16(acc[nt], a0, a1, a2, a3, bh0, bh1);
            mma_f16(acc[nt], a0, a1, a2, a3, bl0, bl1);
        }
    }
    // epilogue
    int ra = mbase + wm * 16 + gid;
    int rb = ra + 8;
#pragma unroll
    for (int nt = 0; nt < 2; nt++) {
        int col = wn * 16 + nt * 8 + tig * 2;
        float b0 = g_bc[col], b1 = g_bc[col + 1];
        float* d = acc[nt];
        *(float2*)&out[(size_t)ra * 64 + col] = make_float2(d[0] + b0, d[1] + b1);
        *(float2*)&out[(size_t)rb * 64 + col] = make_float2(d[2] + b0, d[3] + b1);
    }
}

// ---------------- host ----------------
extern "C" void kernel_launch(void* const* d_in, const int* in_sizes, int n_in,
                              void* d_out, int out_size) {
    const float* node_embeds = (const float*)d_in[0];
    const float* W_hg   = (const float*)d_in[1];
    const float* b_hg   = (const float*)d_in[2];
    const float* W_lin  = (const float*)d_in[3];
    const float* b_lin  = (const float*)d_in[4];
    const float* W_gcn  = (const float*)d_in[5];
    const float* b_gcn  = (const float*)d_in[6];
    const float* W_lin2 = (const float*)d_in[7];
    const float* b_lin2 = (const float*)d_in[8];
    const float* W_lin3 = (const float*)d_in[9];
    const float* b_lin3 = (const float*)d_in[10];
    const float* W_out  = (const float*)d_in[11];
    const float* b_out  = (const float*)d_in[12];
    const void*  ei     = d_in[13];
    const void*  eei    = d_in[14];
    const void*  mei    = d_in[15];
    float* out = (float*)d_out;

    k_initdet<<<256, 256>>>((const unsigned*)ei);
    k_hist<<<2048, 256>>>(ei, eei);
    k_scan<<<2, 1024>>>();
    k_scatter<<<2048, 256>>>(ei, eei);
    k_accA<<<8192, 256>>>();
    k_prep<<<81, 256>>>(W_gcn, W_lin2, W_lin3, W_out, b_gcn, b_lin2, b_lin3, b_out);
    k_chain<<<256, 256>>>(node_embeds, W_hg, b_hg, W_lin, b_lin);

    k_u<<<8192, 256>>>();
    k_agg<<<8192, 256>>>();
    k_motif<<<2048, 256, 32 * SMH_STRIDE * 2>>>(mei, out);
}

// round 16
// speedup vs baseline: 1.5718x; 1.1110x over previous
#include <cuda_runtime.h>
#include <cuda_fp16.h>
#include <cstdint>

#define NN      256
#define EE      65536
#define MMOT    65536
#define NNZ     524288
#define EENNZ   524288
#define SLOPE   0.01f

// ---------------- device scratch (static, no allocations) ----------------
__device__ int   g_is64;
__device__ int   g_bar[8];             // monotonic grid-barrier counters
__device__ float g_small[7 * 65536];   // A, x, y, G, y2, T1(L scratch), spare
#define OFF_A   0
#define OFF_X   (1 * 65536)
#define OFF_Y   (2 * 65536)
#define OFF_G   (3 * 65536)
#define OFF_Y2  (4 * 65536)
#define OFF_T1  (5 * 65536)
__device__ float   g_Wg2[65536];        // W_gcn @ W_lin2
__device__ __half2 g_WcHi[128 * 64];    // fp16 hi of Wc, packed (k,k+1) pairs
__device__ __half2 g_WcLo[128 * 64];    // fp16 lo residual, same packing
__device__ __half  g_T16[65536];        // fp16 T = y2 @ Wg2
__device__ float   g_b2[256];
__device__ float   g_bc[64];
__device__ float   g_dinv[256];
__device__ float   g_dis[EE];
__device__ int     g_cnt_he[EE];
__device__ int     g_cnt_col[EE];
__device__ int     g_off_he[EE + 4];
__device__ int     g_off_col[EE + 4];
__device__ int     g_cur_he[EE];
__device__ int     g_cur_col[EE];
__device__ int     g_dnode[NN];
__device__ int     g_members[NNZ];
__device__ int     g_rows[EENNZ];
__device__ __half  g_w[(size_t)EE * 256];  // dis[e] * mean-agg rows (fp16, 32 MB)
__device__ __half  g_v[(size_t)EE * 256];  // GCN+lin2 output per hyperedge (fp16, 32 MB)

__device__ __forceinline__ int ldidx(const void* p, long long i, int is64) {
    return is64 ? (int)((const long long*)p)[i] : ((const int*)p)[i];
}
__device__ __forceinline__ float lrelu(float x) { return x >= 0.0f ? x : SLOPE * x; }
__device__ __forceinline__ void mma_f16(float* d,
                                        unsigned a0, unsigned a1, unsigned a2, unsigned a3,
                                        unsigned b0, unsigned b1) {
    asm volatile(
        "mma.sync.aligned.m16n8k16.row.col.f32.f16.f16.f32 "
        "{%0,%1,%2,%3},{%4,%5,%6,%7},{%8,%9},{%0,%1,%2,%3};"
        : "+f"(d[0]), "+f"(d[1]), "+f"(d[2]), "+f"(d[3])
        : "r"(a0), "r"(a1), "r"(a2), "r"(a3), "r"(b0), "r"(b1));
}
// accumulate a 16B fp16 chunk into 8 fp32 accumulators
__device__ __forceinline__ void acc_half8(float* acc, uint4 raw) {
    union { uint4 u; __half2 h[4]; } pk;
    pk.u = raw;
#pragma unroll
    for (int r = 0; r < 4; r++) {
        float2 f = __half22float2(pk.h[r]);
        acc[2 * r]     += f.x;
        acc[2 * r + 1] += f.y;
    }
}

// ---------------- init + index dtype detection (fused) ----------------
__global__ void k_initdet(const unsigned* __restrict__ p) {
    int stride = gridDim.x * blockDim.x;
    for (int t = blockIdx.x * blockDim.x + threadIdx.x; t < EE; t += stride) {
        g_small[OFF_A + t]  = 0.0f;
        g_small[OFF_T1 + t] = 0.0f;
        g_cnt_he[t] = 0; g_cnt_col[t] = 0;
        g_cur_he[t] = 0; g_cur_col[t] = 0;
        if (t < NN) g_dnode[t] = 0;
    }
    if (blockIdx.x == 0) {
        __shared__ int nz;
        if (threadIdx.x == 0) nz = 0;
        __syncthreads();
        int any = 0;
        for (int i = threadIdx.x; i < 4096; i += blockDim.x)
            any |= (p[2 * i + 1] != 0u);
        if (any) atomicOr(&nz, 1);
        __syncthreads();
        if (threadIdx.x == 0) g_is64 = nz ? 0 : 1;
    }
}

// ---------------- histograms (split he / ee) ----------------
__global__ void k_hist_he(const void* __restrict__ ei) {
    int is64 = g_is64;
    __shared__ int h[NN];
    for (int i = threadIdx.x; i < NN; i += blockDim.x) h[i] = 0;
    __syncthreads();
    int stride = gridDim.x * blockDim.x;
    for (int i = blockIdx.x * blockDim.x + threadIdx.x; i < NNZ; i += stride) {
        int src = ldidx(ei, i, is64);
        int he  = ldidx(ei, (long long)NNZ + i, is64);
        atomicAdd(&g_cnt_he[he], 1);
        atomicAdd(&h[src], 1);
    }
    __syncthreads();
    for (int i = threadIdx.x; i < NN; i += blockDim.x)
        if (h[i]) atomicAdd(&g_dnode[i], h[i]);
}

__global__ void k_hist_ee(const void* __restrict__ eei) {
    int is64 = g_is64;
    int stride = gridDim.x * blockDim.x;
    for (int j = blockIdx.x * blockDim.x + threadIdx.x; j < EENNZ; j += stride) {
        int col = ldidx(eei, (long long)EENNZ + j, is64);
        atomicAdd(&g_cnt_col[col], 1);
    }
}

// ------- 64K-bin exclusive scans, int4 I/O (1 block each) -------------------
__global__ void k_scan_he() {
    const int4* cnt4 = (const int4*)g_cnt_he;
    int*        off  = g_off_he;
    int4*       off4 = (int4*)off;
    __shared__ int s[1024];
    int t = threadIdx.x;
    int sum = 0;
#pragma unroll
    for (int i = 0; i < 16; i++) {
        int4 c = cnt4[t * 16 + i];
        sum += c.x + c.y + c.z + c.w;
    }
    s[t] = sum;
    __syncthreads();
    for (int o = 1; o < 1024; o <<= 1) {
        int v = (t >= o) ? s[t - o] : 0;
        __syncthreads();
        s[t] += v;
        __syncthreads();
    }
    int run = s[t] - sum;
#pragma unroll
    for (int i = 0; i < 16; i++) {
        int4 c = cnt4[t * 16 + i];
        int4 o;
        o.x = run; run += c.x;
        o.y = run; run += c.y;
        o.z = run; run += c.z;
        o.w = run; run += c.w;
        off4[t * 16 + i] = o;
    }
    if (t == 1023) off[EE] = run;
    if (t < NN) g_dinv[t] = g_dnode[t] > 0 ? 1.0f / (float)g_dnode[t] : 0.0f;
}

__global__ void k_scan_col() {
    const int4* cnt4 = (const int4*)g_cnt_col;
    int*        off  = g_off_col;
    int4*       off4 = (int4*)off;
    __shared__ int s[1024];
    int t = threadIdx.x;
    int sum = 0;
#pragma unroll
    for (int i = 0; i < 16; i++) {
        int4 c = cnt4[t * 16 + i];
        sum += c.x + c.y + c.z + c.w;
    }
    s[t] = sum;
    __syncthreads();
    for (int o = 1; o < 1024; o <<= 1) {
        int v = (t >= o) ? s[t - o] : 0;
        __syncthreads();
        s[t] += v;
        __syncthreads();
    }
    int run = s[t] - sum;
#pragma unroll
    for (int i = 0; i < 16; i++) {
        int4 c = cnt4[t * 16 + i];
        int4 o;
        o.x = run; run += c.x;
        o.y = run; run += c.y;
        o.z = run; run += c.z;
        o.w = run; run += c.w;
        off4[t * 16 + i] = o;
    }
    if (t == 1023) off[EE] = run;
    for (int i = t; i < EE; i += 1024)
        g_dis[i] = rsqrtf((float)(g_cnt_col[i] + 1));  // +1 self loop
}

// ---------------- CSR scatters (split he / ee) ----------------
__global__ void k_scatter_he(const void* __restrict__ ei) {
    int is64 = g_is64;
    int stride = gridDim.x * blockDim.x;
    for (int i = blockIdx.x * blockDim.x + threadIdx.x; i < NNZ; i += stride) {
        int src = ldidx(ei, i, is64);
        int he  = ldidx(ei, (long long)NNZ + i, is64);
        int pos = g_off_he[he] + atomicAdd(&g_cur_he[he], 1);
        g_members[pos] = src;
    }
}

__global__ void k_scatter_ee(const void* __restrict__ eei) {
    int is64 = g_is64;
    int stride = gridDim.x * blockDim.x;
    for (int j = blockIdx.x * blockDim.x + threadIdx.x; j < EENNZ; j += stride) {
        int row = ldidx(eei, j, is64);
        int col = ldidx(eei, (long long)EENNZ + j, is64);
        int pos = g_off_col[col] + atomicAdd(&g_cur_col[col], 1);
        g_rows[pos] = row;
    }
}

// --- A accumulation: WARP per hyperedge (parallel pairs) + diag smem hist ----
__global__ void k_accA() {
    __shared__ float hd[NN];
    for (int i = threadIdx.x; i < NN; i += blockDim.x) hd[i] = 0.0f;
    __syncthreads();
    int w    = (blockIdx.x * blockDim.x + threadIdx.x) >> 5;
    int lane = threadIdx.x & 31;
    if (w < EE) {
        int s = g_off_he[w], e = g_off_he[w + 1];
        int k = e - s;
        if (k > 0) {
            float binv = 1.0f / (float)k;
            for (int p = lane; p < k; p += 32)
                atomicAdd(&hd[g_members[s + p]], binv);
            float* L = &g_small[OFF_T1];
            int tot = k * k;
            for (int p = lane; p < tot; p += 32) {
                int i = p / k, j = p - i * k;
                if (j > i) {
                    int mi = g_members[s + i], mj = g_members[s + j];
                    atomicAdd(&L[mi * 256 + mj], binv);
                }
            }
        }
    }
    __syncthreads();
    for (int i = threadIdx.x; i < NN; i += blockDim.x)
        if (hd[i] != 0.0f) atomicAdd(&g_small[OFF_A + i * 257], hd[i]);
}

// ---------------- 32x32 tile helper (k_prep) ---------------------------------
__device__ void tile_mm(const float* __restrict__ A, const float* __restrict__ B,
                        int lda, int ldb, int row0b, int col0b, int Kk,
                        float o[4], int tid) {
    __shared__ float As[16][34];
    __shared__ float Bs[16][34];
    int tx = tid & 15, ty = tid >> 4;
    float a00 = 0.f, a01 = 0.f, a10 = 0.f, a11 = 0.f;
    for (int kt = 0; kt < Kk; kt += 16) {
        int c = tid & 15, m = tid >> 4;
        As[c][m]      = A[(row0b + m) * lda + kt + c];
        As[c][m + 16] = A[(row0b + m + 16) * lda + kt + c];
        int n = tid & 31, r = tid >> 5;
        Bs[r][n]     = B[(kt + r) * ldb + col0b + n];
        Bs[r + 8][n] = B[(kt + r + 8) * ldb + col0b + n];
        __syncthreads();
#pragma unroll
        for (int kk = 0; kk < 16; kk++) {
            float2 a = *(const float2*)&As[kk][ty * 2];
            float2 b = *(const float2*)&Bs[kk][tx * 2];
            a00 += a.x * b.x; a01 += a.x * b.y;
            a10 += a.y * b.x; a11 += a.y * b.y;
        }
        __syncthreads();
    }
    o[0] = a00; o[1] = a01; o[2] = a10; o[3] = a11;
}

// --- prep: Wg2, WcHi/WcLo (fp16 hi/lo, packed k-pairs), biases ---------------
__global__ void k_prep(const float* __restrict__ Wg, const float* __restrict__ Wl2,
                       const float* __restrict__ Wl3, const float* __restrict__ Wo,
                       const float* __restrict__ bg, const float* __restrict__ bl2,
                       const float* __restrict__ bl3, const float* __restrict__ bo) {
    int b = blockIdx.x;
    int tid = threadIdx.x;
    int tx = tid & 15, ty = tid >> 4;
    if (b < 64) {
        float o[4];
        int r0 = (b >> 3) * 32, c0 = (b & 7) * 32;
        tile_mm(Wg, Wl2, 256, 256, r0, c0, 256, o, tid);
        int row = r0 + ty * 2, col = c0 + tx * 2;
        g_Wg2[row * 256 + col]           = o[0];
        g_Wg2[row * 256 + col + 1]       = o[1];
        g_Wg2[(row + 1) * 256 + col]     = o[2];
        g_Wg2[(row + 1) * 256 + col + 1] = o[3];
    } else if (b < 80) {
        int tb = b - 64;
        float o[4];
        int r0 = (tb >> 1) * 32, c0 = (tb & 1) * 32;
        tile_mm(Wl3, Wo, 128, 64, r0, c0, 128, o, tid);
        int row = r0 + ty * 2, col = c0 + tx * 2;   // row even: (row, row+1) = k-pair
        __half h0 = __float2half_rn(o[0]), h1 = __float2half_rn(o[2]);
        g_WcHi[(row >> 1) * 64 + col] = __halves2half2(h0, h1);
        g_WcLo[(row >> 1) * 64 + col] =
            __floats2half2_rn(o[0] - __half2float(h0), o[2] - __half2float(h1));
        __half h2 = __float2half_rn(o[1]), h3 = __float2half_rn(o[3]);
        g_WcHi[(row >> 1) * 64 + col + 1] = __halves2half2(h2, h3);
        g_WcLo[(row >> 1) * 64 + col + 1] =
            __floats2half2_rn(o[1] - __half2float(h2), o[3] - __half2float(h3));
    } else {
        int j = tid;
        float a = 0.0f;
        for (int k = 0; k < 256; k++) a += bg[k] * Wl2[k * 256 + j];
        g_b2[j] = a + bl2[j];
        if (j < 64) {
            float c = 0.0f;
            for (int k = 0; k < 128; k++) c += bl3[k] * Wo[k * 64 + j];
            g_bc[j] = c + bo[j];
        }
    }
}

// ------ fused 5-GEMM chain + A symmetrize, 256 co-resident blocks ------------
__device__ __forceinline__ void grid_bar(int k) {
    __syncthreads();
    __threadfence();
    if (threadIdx.x == 0) {
        int ticket = atomicAdd(&g_bar[k], 1);
        int target = (ticket / 256 + 1) * 256;
        while (*(volatile int*)&g_bar[k] < target) { }
    }
    __syncthreads();
    __threadfence();
}

// 16x16 tile, one output per thread (256 blocks cover 256x256)
__device__ void stage_gemm(const float* __restrict__ A, const float* __restrict__ B,
                           float* __restrict__ C, __half* __restrict__ Ch,
                           const float* __restrict__ bias,
                           const float* __restrict__ rowscale,
                           int act, int transA) {
    __shared__ float As[16][17];
    __shared__ float Bs[16][17];
    int tid = threadIdx.x;
    int tx = tid & 15, ty = tid >> 4;
    int by = blockIdx.x >> 4, bx = blockIdx.x & 15;
    int row = by * 16 + ty;
    int col = bx * 16 + tx;
    float acc = 0.0f;
    for (int kt = 0; kt < 256; kt += 16) {
        As[ty][tx] = transA ? A[(kt + tx) * 256 + row] : A[row * 256 + kt + tx];
        Bs[ty][tx] = B[(kt + ty) * 256 + col];
        __syncthreads();
#pragma unroll
        for (int kk = 0; kk < 16; kk++) acc += As[ty][kk] * Bs[kk][tx];
        __syncthreads();
    }
    if (rowscale) acc *= rowscale[row];
    if (bias)     acc += bias[col];
    if (act)      acc = lrelu(acc);
    if (Ch) Ch[row * 256 + col] = __float2half_rn(acc);
    else    C[row * 256 + col]  = acc;
}

__global__ __launch_bounds__(256) void k_chain(const float* __restrict__ ne,
                                               const float* __restrict__ W_hg,
                                               const float* __restrict__ b_hg,
                                               const float* __restrict__ W_lin,
                                               const float* __restrict__ b_lin) {
    float* A  = &g_small[OFF_A];
    float* x  = &g_small[OFF_X];
    float* y  = &g_small[OFF_Y];
    float* G  = &g_small[OFF_G];
    float* y2 = &g_small[OFF_Y2];
    // A = L + L^T (each block does 1 row) — consumed after grid_bar(0)
    {
        const float* L = &g_small[OFF_T1];
        int i = blockIdx.x, j = threadIdx.x;
        if (j > i) {
            float sv = L[i * 256 + j] + L[j * 256 + i];
            A[i * 256 + j] = sv;
            A[j * 256 + i] = sv;
        } else if (j == i) {
            A[i * 257] += 2.0f * L[i * 257];
        }
    }
    stage_gemm(ne, W_hg, x, nullptr, nullptr, nullptr, 0, 0);        // x = ne @ W_hg
    grid_bar(0);
    stage_gemm(A, x, y, nullptr, b_hg, g_dinv, 1, 0);                // y = lrelu(dinv*(A@x)+b)
    grid_bar(1);
    stage_gemm(y, y, G, nullptr, nullptr, nullptr, 0, 1);            // G = y^T @ y
    grid_bar(2);
    stage_gemm(G, W_lin, y2, nullptr, b_lin, nullptr, 1, 0);         // y2 = lrelu(G@W_lin+b)
    grid_bar(3);
    stage_gemm(y2, g_Wg2, nullptr, g_T16, nullptr, nullptr, 0, 0);   // T16 = y2 @ Wg2
}

// ------ w[e] = dis[e] * mean_{members} T16[src]  (warp per row, 16B LDG) -----
__global__ void k_u() {
    int e    = blockIdx.x * 8 + (threadIdx.x >> 5);
    int lane = threadIdx.x & 31;
    int s = g_off_he[e], en = g_off_he[e + 1];
    const __half* __restrict__ T = g_T16;
    float acc[8];
#pragma unroll
    for (int q = 0; q < 8; q++) acc[q] = 0.0f;
    int m = s;
    for (; m + 4 <= en; m += 4) {
        int idx[4];
#pragma unroll
        for (int q = 0; q < 4; q++) idx[q] = g_members[m + q];
        uint4 v[4];
#pragma unroll
        for (int q = 0; q < 4; q++)
            v[q] = *(const uint4*)&T[idx[q] * 256 + lane * 8];
#pragma unroll
        for (int q = 0; q < 4; q++) acc_half8(acc, v[q]);
    }
    for (; m < en; m++) {
        uint4 v = *(const uint4*)&T[g_members[m] * 256 + lane * 8];
        acc_half8(acc, v);
    }
    int k = en - s;
    float sc = (k > 0 ? 1.0f / (float)k : 0.0f) * g_dis[e];
    union { uint4 u; __half2 h[4]; } po;
#pragma unroll
    for (int r = 0; r < 4; r++)
        po.h[r] = __floats2half2_rn(acc[2 * r] * sc, acc[2 * r + 1] * sc);
    *(uint4*)&g_w[(size_t)e * 256 + lane * 8] = po.u;
}

// --- GCN agg (warp per row, 16B fp16 LDG, MLP-8) + bias + leaky, fp16 out ----
__global__ void k_agg() {
    int c    = blockIdx.x * 8 + (threadIdx.x >> 5);
    int lane = threadIdx.x & 31;
    float acc[8];
    {   // self loop
        uint4 v = *(const uint4*)&g_w[(size_t)c * 256 + lane * 8];
        union { uint4 u; __half2 h[4]; } pk;
        pk.u = v;
#pragma unroll
        for (int r = 0; r < 4; r++) {
            float2 f = __half22float2(pk.h[r]);
            acc[2 * r] = f.x; acc[2 * r + 1] = f.y;
        }
    }
    int s = g_off_col[c], en = g_off_col[c + 1];
    int j = s;
    for (; j + 8 <= en; j += 8) {
        int idx[8];
#pragma unroll
        for (int q = 0; q < 8; q++) idx[q] = g_rows[j + q];
        uint4 v[8];
#pragma unroll
        for (int q = 0; q < 8; q++)
            v[q] = *(const uint4*)&g_w[(size_t)idx[q] * 256 + lane * 8];
#pragma unroll
        for (int q = 0; q < 8; q++) acc_half8(acc, v[q]);
    }
    for (; j < en; j++) {
        uint4 v = *(const uint4*)&g_w[(size_t)g_rows[j] * 256 + lane * 8];
        acc_half8(acc, v);
    }
    float dc = g_dis[c];
    float4 b0 = *(const float4*)&g_b2[lane * 8];
    float4 b1 = *(const float4*)&g_b2[lane * 8 + 4];
    float bb[8] = {b0.x, b0.y, b0.z, b0.w, b1.x, b1.y, b1.z, b1.w};
    union { uint4 u; __half2 h[4]; } po;
#pragma unroll
    for (int r = 0; r < 4; r++)
        po.h[r] = __floats2half2_rn(lrelu(dc * acc[2 * r] + bb[2 * r]),
                                    lrelu(dc * acc[2 * r + 1] + bb[2 * r + 1]));
    *(uint4*)&g_v[(size_t)c * 256 + lane * 8] = po.u;
}

// ------- motif: min(3 fp16 rows) -> fp16 MMA (Wc hi/lo 2-pass) ---------------
#define SMH_STRIDE 264
__global__ __launch_bounds__(256, 5) void k_motif(const void* __restrict__ mei,
                                                  float* __restrict__ out) {
    extern __shared__ __half smh[];    // [32][SMH_STRIDE] fp16 min values
    __shared__ int sIdx[96];
    int tid = threadIdx.x, lane = tid & 31, wid = tid >> 5;
    int is64 = g_is64;
    int mbase = blockIdx.x * 32;
    if (tid < 96) sIdx[tid] = ldidx(mei, 3LL * mbase + tid, is64);
    __syncthreads();
    // stage 1: min of 3 fp16 rows -> fp16 smem (exact, __hmin2)
#pragma unroll
    for (int mm = wid * 4; mm < wid * 4 + 4; mm++) {
        const __half* __restrict__ r0 = &g_v[(size_t)sIdx[3 * mm]     * 256];
        const __half* __restrict__ r1 = &g_v[(size_t)sIdx[3 * mm + 1] * 256];
        const __half* __restrict__ r2 = &g_v[(size_t)sIdx[3 * mm + 2] * 256];
        union { uint4 u; __half2 h[4]; } A, B, C, O;
        A.u = *(const uint4*)&r0[lane * 8];
        B.u = *(const uint4*)&r1[lane * 8];
        C.u = *(const uint4*)&r2[lane * 8];
#pragma unroll
        for (int q = 0; q < 4; q++)
            O.h[q] = __hmin2(__hmin2(A.h[q], B.h[q]), C.h[q]);
        *(uint4*)&smh[mm * SMH_STRIDE + lane * 8] = O.u;
    }
    __syncthreads();
    // stage 2: [32 x 256] @ [256 x 64] via m16n8k16 f16, hi+lo passes
    int wm = wid >> 2, wn = wid & 3;
    int gid = lane >> 2, tig = lane & 3;
    float acc[2][4];
#pragma unroll
    for (int nt = 0; nt < 2; nt++)
#pragma unroll
        for (int q = 0; q < 4; q++) acc[nt][q] = 0.0f;
    const __half2* __restrict__ Whi = g_WcHi;
    const __half2* __restrict__ Wlo = g_WcLo;
    int mr = wm * 16 + gid;
    for (int k0 = 0; k0 < 256; k0 += 16) {
        unsigned a0 = *(const unsigned*)&smh[mr * SMH_STRIDE + k0 + 2 * tig];
        unsigned a1 = *(const unsigned*)&smh[(mr + 8) * SMH_STRIDE + k0 + 2 * tig];
        unsigned a2 = *(const unsigned*)&smh[mr * SMH_STRIDE + k0 + 8 + 2 * tig];
        unsigned a3 = *(const unsigned*)&smh[(mr + 8) * SMH_STRIDE + k0 + 8 + 2 * tig];
        int kb = (k0 >> 1) + tig;
#pragma unroll
        for (int nt = 0; nt < 2; nt++) {
            int n = wn * 16 + nt * 8 + gid;
            unsigned bh0 = *(const unsigned*)&Whi[kb * 64 + n];
            unsigned bh1 = *(const unsigned*)&Whi[(kb + 4) * 64 + n];
            unsigned bl0 = *(const unsigned*)&Wlo[kb * 64 + n];
            unsigned bl1 = *(const unsigned*)&Wlo[(kb + 4) * 64 + n];
            mma_f16(acc[nt], a0, a1, a2, a3, bh0, bh1);
            mma_f16(acc[nt], a0, a1, a2, a3, bl0, bl1);
        }
    }
    // epilogue
    int ra = mbase + wm * 16 + gid;
    int rb = ra + 8;
#pragma unroll
    for (int nt = 0; nt < 2; nt++) {
        int col = wn * 16 + nt * 8 + tig * 2;
        float b0 = g_bc[col], b1 = g_bc[col + 1];
        float* d = acc[nt];
        *(float2*)&out[(size_t)ra * 64 + col] = make_float2(d[0] + b0, d[1] + b1);
        *(float2*)&out[(size_t)rb * 64 + col] = make_float2(d[2] + b0, d[3] + b1);
    }
}

// ---------------- host ----------------
extern "C" void kernel_launch(void* const* d_in, const int* in_sizes, int n_in,
                              void* d_out, int out_size) {
    const float* node_embeds = (const float*)d_in[0];
    const float* W_hg   = (const float*)d_in[1];
    const float* b_hg   = (const float*)d_in[2];
    const float* W_lin  = (const float*)d_in[3];
    const float* b_lin  = (const float*)d_in[4];
    const float* W_gcn  = (const float*)d_in[5];
    const float* b_gcn  = (const float*)d_in[6];
    const float* W_lin2 = (const float*)d_in[7];
    const float* b_lin2 = (const float*)d_in[8];
    const float* W_lin3 = (const float*)d_in[9];
    const float* b_lin3 = (const float*)d_in[10];
    const float* W_out  = (const float*)d_in[11];
    const float* b_out  = (const float*)d_in[12];
    const void*  ei     = d_in[13];
    const void*  eei    = d_in[14];
    const void*  mei    = d_in[15];
    float* out = (float*)d_out;

    static int inited = 0;
    static cudaStream_t s1, s2;
    static cudaEvent_t evRoot, evPrep, evScanC, evScatE;
    if (!inited) {
        cudaStreamCreateWithFlags(&s1, cudaStreamNonBlocking);
        cudaStreamCreateWithFlags(&s2, cudaStreamNonBlocking);
        cudaEventCreateWithFlags(&evRoot,  cudaEventDisableTiming);
        cudaEventCreateWithFlags(&evPrep,  cudaEventDisableTiming);
        cudaEventCreateWithFlags(&evScanC, cudaEventDisableTiming);
        cudaEventCreateWithFlags(&evScatE, cudaEventDisableTiming);
        inited = 1;
    }

    // root
    k_initdet<<<256, 256>>>((const unsigned*)ei);
    cudaEventRecord(evRoot, 0);
    cudaStreamWaitEvent(s1, evRoot, 0);
    cudaStreamWaitEvent(s2, evRoot, 0);

    // branch ee (s1): hist_ee -> scan_col (g_dis) -> scatter_ee
    k_hist_ee<<<1024, 256, 0, s1>>>(eei);
    k_scan_col<<<1, 1024, 0, s1>>>();
    cudaEventRecord(evScanC, s1);
    k_scatter_ee<<<1024, 256, 0, s1>>>(eei);
    cudaEventRecord(evScatE, s1);

    // branch prep (s2)
    k_prep<<<81, 256, 0, s2>>>(W_gcn, W_lin2, W_lin3, W_out, b_gcn, b_lin2, b_lin3, b_out);
    cudaEventRecord(evPrep, s2);

    // branch he (default): hist_he -> scan_he -> scatter_he -> accA
    k_hist_he<<<1024, 256>>>(ei);
    k_scan_he<<<1, 1024>>>();
    k_scatter_he<<<1024, 256>>>(ei);
    k_accA<<<8192, 256>>>();

    // chain needs L (accA), g_dinv (scan_he), Wg2 (prep)
    cudaStreamWaitEvent(0, evPrep, 0);
    k_chain<<<256, 256>>>(node_embeds, W_hg, b_hg, W_lin, b_lin);

    // k_u needs T16 (chain), he CSR, g_dis (scan_col)
    cudaStreamWaitEvent(0, evScanC, 0);
    k_u<<<8192, 256>>>();

    // k_agg needs g_w (k_u), ee CSR (scatter_ee), g_b2 (prep, already joined)
    cudaStreamWaitEvent(0, evScatE, 0);
    k_agg<<<8192, 256>>>();

    k_motif<<<2048, 256, 32 * SMH_STRIDE * 2>>>(mei, out);
}

// round 17
// speedup vs baseline: 1.7137x; 1.0903x over previous
#include <cuda_runtime.h>
#include <cuda_fp16.h>
#include <cstdint>

#define NN      256
#define EE      65536
#define MMOT    65536
#define NNZ     524288
#define EENNZ   524288
#define SLOPE   0.01f

// ---------------- device scratch (static, no allocations) ----------------
__device__ int   g_is64;
__device__ int   g_bar[8];             // monotonic grid-barrier counters
__device__ float g_small[7 * 65536];   // A, x, y, G, y2, T1(L scratch), spare
#define OFF_A   0
#define OFF_X   (1 * 65536)
#define OFF_Y   (2 * 65536)
#define OFF_G   (3 * 65536)
#define OFF_Y2  (4 * 65536)
#define OFF_T1  (5 * 65536)
__device__ float   g_Wg2[65536];        // W_gcn @ W_lin2
__device__ __half2 g_WcHi[128 * 64];    // fp16 hi of Wc, packed (k,k+1) pairs
__device__ __half2 g_WcLo[128 * 64];    // fp16 lo residual, same packing
__device__ __half  g_T16[65536];        // fp16 T = y2 @ Wg2
__device__ float   g_b2[256];
__device__ float   g_bc[64];
__device__ float   g_dinv[256];
__device__ float   g_dis[EE];
__device__ int     g_cnt_he[EE];
__device__ int     g_cnt_col[EE];
__device__ int     g_off_he[EE + 4];
__device__ int     g_off_col[EE + 4];
__device__ int     g_cur_he[EE];
__device__ int     g_cur_col[EE];
__device__ int     g_dnode[NN];
__device__ int     g_members[NNZ];
__device__ int     g_rows[EENNZ];
__device__ __half  g_w[(size_t)EE * 256];  // dis[e] * mean-agg rows (fp16, 32 MB)
__device__ __half  g_v[(size_t)EE * 256];  // GCN+lin2 output per hyperedge (fp16, 32 MB)

__device__ __forceinline__ int ldidx(const void* p, long long i, int is64) {
    return is64 ? (int)((const long long*)p)[i] : ((const int*)p)[i];
}
__device__ __forceinline__ float lrelu(float x) { return x >= 0.0f ? x : SLOPE * x; }
__device__ __forceinline__ void mma_f16(float* d,
                                        unsigned a0, unsigned a1, unsigned a2, unsigned a3,
                                        unsigned b0, unsigned b1) {
    asm volatile(
        "mma.sync.aligned.m16n8k16.row.col.f32.f16.f16.f32 "
        "{%0,%1,%2,%3},{%4,%5,%6,%7},{%8,%9},{%0,%1,%2,%3};"
        : "+f"(d[0]), "+f"(d[1]), "+f"(d[2]), "+f"(d[3])
        : "r"(a0), "r"(a1), "r"(a2), "r"(a3), "r"(b0), "r"(b1));
}
// accumulate a 16B fp16 chunk into 8 fp32 accumulators
__device__ __forceinline__ void acc_half8(float* acc, uint4 raw) {
    union { uint4 u; __half2 h[4]; } pk;
    pk.u = raw;
#pragma unroll
    for (int r = 0; r < 4; r++) {
        float2 f = __half22float2(pk.h[r]);
        acc[2 * r]     += f.x;
        acc[2 * r + 1] += f.y;
    }
}

// ---------------- index dtype detection (1 block, tiny) ----------------
__global__ void k_det(const unsigned* __restrict__ p) {
    __shared__ int nz;
    if (threadIdx.x == 0) nz = 0;
    __syncthreads();
    int any = 0;
    for (int i = threadIdx.x; i < 4096; i += blockDim.x)
        any |= (p[2 * i + 1] != 0u);
    if (any) atomicOr(&nz, 1);
    __syncthreads();
    if (threadIdx.x == 0) g_is64 = nz ? 0 : 1;
}

// ---------------- zeroing (split per branch) ----------------
__global__ void k_zero_he() {
    int stride = gridDim.x * blockDim.x;
    for (int t = blockIdx.x * blockDim.x + threadIdx.x; t < EE; t += stride) {
        g_small[OFF_A + t]  = 0.0f;
        g_small[OFF_T1 + t] = 0.0f;
        g_cnt_he[t] = 0; g_cur_he[t] = 0;
        if (t < NN) g_dnode[t] = 0;
    }
}
__global__ void k_zero_ee() {
    int stride = gridDim.x * blockDim.x;
    for (int t = blockIdx.x * blockDim.x + threadIdx.x; t < EE; t += stride) {
        g_cnt_col[t] = 0; g_cur_col[t] = 0;
    }
}

// ---------------- histograms (split he / ee) ----------------
__global__ void k_hist_he(const void* __restrict__ ei) {
    int is64 = g_is64;
    __shared__ int h[NN];
    for (int i = threadIdx.x; i < NN; i += blockDim.x) h[i] = 0;
    __syncthreads();
    int stride = gridDim.x * blockDim.x;
    for (int i = blockIdx.x * blockDim.x + threadIdx.x; i < NNZ; i += stride) {
        int src = ldidx(ei, i, is64);
        int he  = ldidx(ei, (long long)NNZ + i, is64);
        atomicAdd(&g_cnt_he[he], 1);
        atomicAdd(&h[src], 1);
    }
    __syncthreads();
    for (int i = threadIdx.x; i < NN; i += blockDim.x)
        if (h[i]) atomicAdd(&g_dnode[i], h[i]);
}

__global__ void k_hist_ee(const void* __restrict__ eei) {
    int is64 = g_is64;
    int stride = gridDim.x * blockDim.x;
    for (int j = blockIdx.x * blockDim.x + threadIdx.x; j < EENNZ; j += stride) {
        int col = ldidx(eei, (long long)EENNZ + j, is64);
        atomicAdd(&g_cnt_col[col], 1);
    }
}

// ------- 64K-bin exclusive scans, int4 I/O (1 block each) -------------------
__global__ void k_scan_he() {
    const int4* cnt4 = (const int4*)g_cnt_he;
    int*        off  = g_off_he;
    int4*       off4 = (int4*)off;
    __shared__ int s[1024];
    int t = threadIdx.x;
    int sum = 0;
#pragma unroll
    for (int i = 0; i < 16; i++) {
        int4 c = cnt4[t * 16 + i];
        sum += c.x + c.y + c.z + c.w;
    }
    s[t] = sum;
    __syncthreads();
    for (int o = 1; o < 1024; o <<= 1) {
        int v = (t >= o) ? s[t - o] : 0;
        __syncthreads();
        s[t] += v;
        __syncthreads();
    }
    int run = s[t] - sum;
#pragma unroll
    for (int i = 0; i < 16; i++) {
        int4 c = cnt4[t * 16 + i];
        int4 o;
        o.x = run; run += c.x;
        o.y = run; run += c.y;
        o.z = run; run += c.z;
        o.w = run; run += c.w;
        off4[t * 16 + i] = o;
    }
    if (t == 1023) off[EE] = run;
    if (t < NN) g_dinv[t] = g_dnode[t] > 0 ? 1.0f / (float)g_dnode[t] : 0.0f;
}

__global__ void k_scan_col() {
    const int4* cnt4 = (const int4*)g_cnt_col;
    int*        off  = g_off_col;
    int4*       off4 = (int4*)off;
    __shared__ int s[1024];
    int t = threadIdx.x;
    int sum = 0;
#pragma unroll
    for (int i = 0; i < 16; i++) {
        int4 c = cnt4[t * 16 + i];
        sum += c.x + c.y + c.z + c.w;
    }
    s[t] = sum;
    __syncthreads();
    for (int o = 1; o < 1024; o <<= 1) {
        int v = (t >= o) ? s[t - o] : 0;
        __syncthreads();
        s[t] += v;
        __syncthreads();
    }
    int run = s[t] - sum;
#pragma unroll
    for (int i = 0; i < 16; i++) {
        int4 c = cnt4[t * 16 + i];
        int4 o;
        o.x = run; run += c.x;
        o.y = run; run += c.y;
        o.z = run; run += c.z;
        o.w = run; run += c.w;
        off4[t * 16 + i] = o;
    }
    if (t == 1023) off[EE] = run;
    for (int i = t; i < EE; i += 1024)
        g_dis[i] = rsqrtf((float)(g_cnt_col[i] + 1));  // +1 self loop
}

// ---------------- CSR scatters (split he / ee) ----------------
__global__ void k_scatter_he(const void* __restrict__ ei) {
    int is64 = g_is64;
    int stride = gridDim.x * blockDim.x;
    for (int i = blockIdx.x * blockDim.x + threadIdx.x; i < NNZ; i += stride) {
        int src = ldidx(ei, i, is64);
        int he  = ldidx(ei, (long long)NNZ + i, is64);
        int pos = g_off_he[he] + atomicAdd(&g_cur_he[he], 1);
        g_members[pos] = src;
    }
}

__global__ void k_scatter_ee(const void* __restrict__ eei) {
    int is64 = g_is64;
    int stride = gridDim.x * blockDim.x;
    for (int j = blockIdx.x * blockDim.x + threadIdx.x; j < EENNZ; j += stride) {
        int row = ldidx(eei, j, is64);
        int col = ldidx(eei, (long long)EENNZ + j, is64);
        int pos = g_off_col[col] + atomicAdd(&g_cur_col[col], 1);
        g_rows[pos] = row;
    }
}

// --- A accumulation: WARP per hyperedge (parallel pairs) + diag smem hist ----
__global__ void k_accA() {
    __shared__ float hd[NN];
    for (int i = threadIdx.x; i < NN; i += blockDim.x) hd[i] = 0.0f;
    __syncthreads();
    int w    = (blockIdx.x * blockDim.x + threadIdx.x) >> 5;
    int lane = threadIdx.x & 31;
    if (w < EE) {
        int s = g_off_he[w], e = g_off_he[w + 1];
        int k = e - s;
        if (k > 0) {
            float binv = 1.0f / (float)k;
            for (int p = lane; p < k; p += 32)
                atomicAdd(&hd[g_members[s + p]], binv);
            float* L = &g_small[OFF_T1];
            int tot = k * k;
            for (int p = lane; p < tot; p += 32) {
                int i = p / k, j = p - i * k;
                if (j > i) {
                    int mi = g_members[s + i], mj = g_members[s + j];
                    atomicAdd(&L[mi * 256 + mj], binv);
                }
            }
        }
    }
    __syncthreads();
    for (int i = threadIdx.x; i < NN; i += blockDim.x)
        if (hd[i] != 0.0f) atomicAdd(&g_small[OFF_A + i * 257], hd[i]);
}

// ---------------- 32x32 tile helper (k_prep) ---------------------------------
__device__ void tile_mm(const float* __restrict__ A, const float* __restrict__ B,
                        int lda, int ldb, int row0b, int col0b, int Kk,
                        float o[4], int tid) {
    __shared__ float As[16][34];
    __shared__ float Bs[16][34];
    int tx = tid & 15, ty = tid >> 4;
    float a00 = 0.f, a01 = 0.f, a10 = 0.f, a11 = 0.f;
    for (int kt = 0; kt < Kk; kt += 16) {
        int c = tid & 15, m = tid >> 4;
        As[c][m]      = A[(row0b + m) * lda + kt + c];
        As[c][m + 16] = A[(row0b + m + 16) * lda + kt + c];
        int n = tid & 31, r = tid >> 5;
        Bs[r][n]     = B[(kt + r) * ldb + col0b + n];
        Bs[r + 8][n] = B[(kt + r + 8) * ldb + col0b + n];
        __syncthreads();
#pragma unroll
        for (int kk = 0; kk < 16; kk++) {
            float2 a = *(const float2*)&As[kk][ty * 2];
            float2 b = *(const float2*)&Bs[kk][tx * 2];
            a00 += a.x * b.x; a01 += a.x * b.y;
            a10 += a.y * b.x; a11 += a.y * b.y;
        }
        __syncthreads();
    }
    o[0] = a00; o[1] = a01; o[2] = a10; o[3] = a11;
}

// --- prep: Wg2, WcHi/WcLo (fp16 hi/lo, packed k-pairs), biases ---------------
__global__ void k_prep(const float* __restrict__ Wg, const float* __restrict__ Wl2,
                       const float* __restrict__ Wl3, const float* __restrict__ Wo,
                       const float* __restrict__ bg, const float* __restrict__ bl2,
                       const float* __restrict__ bl3, const float* __restrict__ bo) {
    int b = blockIdx.x;
    int tid = threadIdx.x;
    int tx = tid & 15, ty = tid >> 4;
    if (b < 64) {
        float o[4];
        int r0 = (b >> 3) * 32, c0 = (b & 7) * 32;
        tile_mm(Wg, Wl2, 256, 256, r0, c0, 256, o, tid);
        int row = r0 + ty * 2, col = c0 + tx * 2;
        g_Wg2[row * 256 + col]           = o[0];
        g_Wg2[row * 256 + col + 1]       = o[1];
        g_Wg2[(row + 1) * 256 + col]     = o[2];
        g_Wg2[(row + 1) * 256 + col + 1] = o[3];
    } else if (b < 80) {
        int tb = b - 64;
        float o[4];
        int r0 = (tb >> 1) * 32, c0 = (tb & 1) * 32;
        tile_mm(Wl3, Wo, 128, 64, r0, c0, 128, o, tid);
        int row = r0 + ty * 2, col = c0 + tx * 2;   // row even: (row, row+1) = k-pair
        __half h0 = __float2half_rn(o[0]), h1 = __float2half_rn(o[2]);
        g_WcHi[(row >> 1) * 64 + col] = __halves2half2(h0, h1);
        g_WcLo[(row >> 1) * 64 + col] =
            __floats2half2_rn(o[0] - __half2float(h0), o[2] - __half2float(h1));
        __half h2 = __float2half_rn(o[1]), h3 = __float2half_rn(o[3]);
        g_WcHi[(row >> 1) * 64 + col + 1] = __halves2half2(h2, h3);
        g_WcLo[(row >> 1) * 64 + col + 1] =
            __floats2half2_rn(o[1] - __half2float(h2), o[3] - __half2float(h3));
    } else {
        int j = tid;
        float a = 0.0f;
        for (int k = 0; k < 256; k++) a += bg[k] * Wl2[k * 256 + j];
        g_b2[j] = a + bl2[j];
        if (j < 64) {
            float c = 0.0f;
            for (int k = 0; k < 128; k++) c += bl3[k] * Wo[k * 64 + j];
            g_bc[j] = c + bo[j];
        }
    }
}

// ------ 16x16-tile GEMM stage (one output per thread, 256 blocks) ------------
__device__ void stage_gemm(const float* __restrict__ A, const float* __restrict__ B,
                           float* __restrict__ C, __half* __restrict__ Ch,
                           const float* __restrict__ bias,
                           const float* __restrict__ rowscale,
                           int act, int transA) {
    __shared__ float As[16][17];
    __shared__ float Bs[16][17];
    int tid = threadIdx.x;
    int tx = tid & 15, ty = tid >> 4;
    int by = blockIdx.x >> 4, bx = blockIdx.x & 15;
    int row = by * 16 + ty;
    int col = bx * 16 + tx;
    float acc = 0.0f;
    for (int kt = 0; kt < 256; kt += 16) {
        As[ty][tx] = transA ? A[(kt + tx) * 256 + row] : A[row * 256 + kt + tx];
        Bs[ty][tx] = B[(kt + ty) * 256 + col];
        __syncthreads();
#pragma unroll
        for (int kk = 0; kk < 16; kk++) acc += As[ty][kk] * Bs[kk][tx];
        __syncthreads();
    }
    if (rowscale) acc *= rowscale[row];
    if (bias)     acc += bias[col];
    if (act)      acc = lrelu(acc);
    if (Ch) Ch[row * 256 + col] = __float2half_rn(acc);
    else    C[row * 256 + col]  = acc;
}

// x = ne @ W_hg (standalone, off the critical path on s2)
__global__ __launch_bounds__(256) void k_xgemm(const float* __restrict__ ne,
                                               const float* __restrict__ W_hg) {
    stage_gemm(ne, W_hg, &g_small[OFF_X], nullptr, nullptr, nullptr, 0, 0);
}

// ------ fused 4-GEMM chain + A symmetrize, 256 co-resident blocks ------------
__device__ __forceinline__ void grid_bar(int k) {
    __syncthreads();
    __threadfence();
    if (threadIdx.x == 0) {
        int ticket = atomicAdd(&g_bar[k], 1);
        int target = (ticket / 256 + 1) * 256;
        while (*(volatile int*)&g_bar[k] < target) { }
    }
    __syncthreads();
    __threadfence();
}

__global__ __launch_bounds__(256) void k_chain(const float* __restrict__ b_hg,
                                               const float* __restrict__ W_lin,
                                               const float* __restrict__ b_lin) {
    float* A  = &g_small[OFF_A];
    float* x  = &g_small[OFF_X];
    float* y  = &g_small[OFF_Y];
    float* G  = &g_small[OFF_G];
    float* y2 = &g_small[OFF_Y2];
    // A = L + L^T (each block does 1 row) — consumed after grid_bar(0)
    {
        const float* L = &g_small[OFF_T1];
        int i = blockIdx.x, j = threadIdx.x;
        if (j > i) {
            float sv = L[i * 256 + j] + L[j * 256 + i];
            A[i * 256 + j] = sv;
            A[j * 256 + i] = sv;
        } else if (j == i) {
            A[i * 257] += 2.0f * L[i * 257];
        }
    }
    grid_bar(0);
    stage_gemm(A, x, y, nullptr, b_hg, g_dinv, 1, 0);                // y = lrelu(dinv*(A@x)+b)
    grid_bar(1);
    stage_gemm(y, y, G, nullptr, nullptr, nullptr, 0, 1);            // G = y^T @ y
    grid_bar(2);
    stage_gemm(G, W_lin, y2, nullptr, b_lin, nullptr, 1, 0);         // y2 = lrelu(G@W_lin+b)
    grid_bar(3);
    stage_gemm(y2, g_Wg2, nullptr, g_T16, nullptr, nullptr, 0, 0);   // T16 = y2 @ Wg2
}

// ------ w[e] = dis[e] * mean_{members} T16[src]  (warp per row, 16B LDG) -----
__global__ void k_u() {
    int e    = blockIdx.x * 8 + (threadIdx.x >> 5);
    int lane = threadIdx.x & 31;
    int s = g_off_he[e], en = g_off_he[e + 1];
    const __half* __restrict__ T = g_T16;
    float acc[8];
#pragma unroll
    for (int q = 0; q < 8; q++) acc[q] = 0.0f;
    int m = s;
    for (; m + 4 <= en; m += 4) {
        int idx[4];
#pragma unroll
        for (int q = 0; q < 4; q++) idx[q] = g_members[m + q];
        uint4 v[4];
#pragma unroll
        for (int q = 0; q < 4; q++)
            v[q] = *(const uint4*)&T[idx[q] * 256 + lane * 8];
#pragma unroll
        for (int q = 0; q < 4; q++) acc_half8(acc, v[q]);
    }
    for (; m < en; m++) {
        uint4 v = *(const uint4*)&T[g_members[m] * 256 + lane * 8];
        acc_half8(acc, v);
    }
    int k = en - s;
    float sc = (k > 0 ? 1.0f / (float)k : 0.0f) * g_dis[e];
    union { uint4 u; __half2 h[4]; } po;
#pragma unroll
    for (int r = 0; r < 4; r++)
        po.h[r] = __floats2half2_rn(acc[2 * r] * sc, acc[2 * r + 1] * sc);
    *(uint4*)&g_w[(size_t)e * 256 + lane * 8] = po.u;
}

// --- GCN agg (warp per row, 16B fp16 LDG, MLP-8) + bias + leaky, fp16 out ----
__global__ void k_agg() {
    int c    = blockIdx.x * 8 + (threadIdx.x >> 5);
    int lane = threadIdx.x & 31;
    float acc[8];
    {   // self loop
        uint4 v = *(const uint4*)&g_w[(size_t)c * 256 + lane * 8];
        union { uint4 u; __half2 h[4]; } pk;
        pk.u = v;
#pragma unroll
        for (int r = 0; r < 4; r++) {
            float2 f = __half22float2(pk.h[r]);
            acc[2 * r] = f.x; acc[2 * r + 1] = f.y;
        }
    }
    int s = g_off_col[c], en = g_off_col[c + 1];
    int j = s;
    for (; j + 8 <= en; j += 8) {
        int idx[8];
#pragma unroll
        for (int q = 0; q < 8; q++) idx[q] = g_rows[j + q];
        uint4 v[8];
#pragma unroll
        for (int q = 0; q < 8; q++)
            v[q] = *(const uint4*)&g_w[(size_t)idx[q] * 256 + lane * 8];
#pragma unroll
        for (int q = 0; q < 8; q++) acc_half8(acc, v[q]);
    }
    for (; j < en; j++) {
        uint4 v = *(const uint4*)&g_w[(size_t)g_rows[j] * 256 + lane * 8];
        acc_half8(acc, v);
    }
    float dc = g_dis[c];
    float4 b0 = *(const float4*)&g_b2[lane * 8];
    float4 b1 = *(const float4*)&g_b2[lane * 8 + 4];
    float bb[8] = {b0.x, b0.y, b0.z, b0.w, b1.x, b1.y, b1.z, b1.w};
    union { uint4 u; __half2 h[4]; } po;
#pragma unroll
    for (int r = 0; r < 4; r++)
        po.h[r] = __floats2half2_rn(lrelu(dc * acc[2 * r] + bb[2 * r]),
                                    lrelu(dc * acc[2 * r + 1] + bb[2 * r + 1]));
    *(uint4*)&g_v[(size_t)c * 256 + lane * 8] = po.u;
}

// ------- motif: min(3 fp16 rows) -> fp16 MMA (Wc hi/lo 2-pass) ---------------
#define SMH_STRIDE 264
__global__ __launch_bounds__(256, 5) void k_motif(const void* __restrict__ mei,
                                                  float* __restrict__ out) {
    extern __shared__ __half smh[];    // [32][SMH_STRIDE] fp16 min values
    __shared__ int sIdx[96];
    int tid = threadIdx.x, lane = tid & 31, wid = tid >> 5;
    int is64 = g_is64;
    int mbase = blockIdx.x * 32;
    if (tid < 96) sIdx[tid] = ldidx(mei, 3LL * mbase + tid, is64);
    __syncthreads();
    // stage 1: min of 3 fp16 rows -> fp16 smem (exact, __hmin2)
#pragma unroll
    for (int mm = wid * 4; mm < wid * 4 + 4; mm++) {
        const __half* __restrict__ r0 = &g_v[(size_t)sIdx[3 * mm]     * 256];
        const __half* __restrict__ r1 = &g_v[(size_t)sIdx[3 * mm + 1] * 256];
        const __half* __restrict__ r2 = &g_v[(size_t)sIdx[3 * mm + 2] * 256];
        union { uint4 u; __half2 h[4]; } A, B, C, O;
        A.u = *(const uint4*)&r0[lane * 8];
        B.u = *(const uint4*)&r1[lane * 8];
        C.u = *(const uint4*)&r2[lane * 8];
#pragma unroll
        for (int q = 0; q < 4; q++)
            O.h[q] = __hmin2(__hmin2(A.h[q], B.h[q]), C.h[q]);
        *(uint4*)&smh[mm * SMH_STRIDE + lane * 8] = O.u;
    }
    __syncthreads();
    // stage 2: [32 x 256] @ [256 x 64] via m16n8k16 f16, hi+lo passes
    int wm = wid >> 2, wn = wid & 3;
    int gid = lane >> 2, tig = lane & 3;
    float acc[2][4];
#pragma unroll
    for (int nt = 0; nt < 2; nt++)
#pragma unroll
        for (int q = 0; q < 4; q++) acc[nt][q] = 0.0f;
    const __half2* __restrict__ Whi = g_WcHi;
    const __half2* __restrict__ Wlo = g_WcLo;
    int mr = wm * 16 + gid;
    for (int k0 = 0; k0 < 256; k0 += 16) {
        unsigned a0 = *(const unsigned*)&smh[mr * SMH_STRIDE + k0 + 2 * tig];
        unsigned a1 = *(const unsigned*)&smh[(mr + 8) * SMH_STRIDE + k0 + 2 * tig];
        unsigned a2 = *(const unsigned*)&smh[mr * SMH_STRIDE + k0 + 8 + 2 * tig];
        unsigned a3 = *(const unsigned*)&smh[(mr + 8) * SMH_STRIDE + k0 + 8 + 2 * tig];
        int kb = (k0 >> 1) + tig;
#pragma unroll
        for (int nt = 0; nt < 2; nt++) {
            int n = wn * 16 + nt * 8 + gid;
            unsigned bh0 = *(const unsigned*)&Whi[kb * 64 + n];
            unsigned bh1 = *(const unsigned*)&Whi[(kb + 4) * 64 + n];
            unsigned bl0 = *(const unsigned*)&Wlo[kb * 64 + n];
            unsigned bl1 = *(const unsigned*)&Wlo[(kb + 4) * 64 + n];
            mma_f16(acc[nt], a0, a1, a2, a3, bh0, bh1);
            mma_f16(acc[nt], a0, a1, a2, a3, bl0, bl1);
        }
    }
    // epilogue
    int ra = mbase + wm * 16 + gid;
    int rb = ra + 8;
#pragma unroll
    for (int nt = 0; nt < 2; nt++) {
        int col = wn * 16 + nt * 8 + tig * 2;
        float b0 = g_bc[col], b1 = g_bc[col + 1];
        float* d = acc[nt];
        *(float2*)&out[(size_t)ra * 64 + col] = make_float2(d[0] + b0, d[1] + b1);
        *(float2*)&out[(size_t)rb * 64 + col] = make_float2(d[2] + b0, d[3] + b1);
    }
}

// ---------------- host ----------------
extern "C" void kernel_launch(void* const* d_in, const int* in_sizes, int n_in,
                              void* d_out, int out_size) {
    const float* node_embeds = (const float*)d_in[0];
    const float* W_hg   = (const float*)d_in[1];
    const float* b_hg   = (const float*)d_in[2];
    const float* W_lin  = (const float*)d_in[3];
    const float* b_lin  = (const float*)d_in[4];
    const float* W_gcn  = (const float*)d_in[5];
    const float* b_gcn  = (const float*)d_in[6];
    const float* W_lin2 = (const float*)d_in[7];
    const float* b_lin2 = (const float*)d_in[8];
    const float* W_lin3 = (const float*)d_in[9];
    const float* b_lin3 = (const float*)d_in[10];
    const float* W_out  = (const float*)d_in[11];
    const float* b_out  = (const float*)d_in[12];
    const void*  ei     = d_in[13];
    const void*  eei    = d_in[14];
    const void*  mei    = d_in[15];
    float* out = (float*)d_out;

    static int inited = 0;
    static cudaStream_t s1, s2;
    static cudaEvent_t evDet, evPrep, evScanC, evScatE;
    if (!inited) {
        cudaStreamCreateWithFlags(&s1, cudaStreamNonBlocking);
        cudaStreamCreateWithFlags(&s2, cudaStreamNonBlocking);
        cudaEventCreateWithFlags(&evDet,   cudaEventDisableTiming);
        cudaEventCreateWithFlags(&evPrep,  cudaEventDisableTiming);
        cudaEventCreateWithFlags(&evScanC, cudaEventDisableTiming);
        cudaEventCreateWithFlags(&evScatE, cudaEventDisableTiming);
        inited = 1;
    }

    // root: detection only (1 tiny block)
    k_det<<<1, 256>>>((const unsigned*)ei);
    cudaEventRecord(evDet, 0);
    cudaStreamWaitEvent(s1, evDet, 0);
    cudaStreamWaitEvent(s2, evDet, 0);

    // branch ee (s1): zero -> hist_ee -> scan_col (g_dis) -> scatter_ee
    k_zero_ee<<<128, 256, 0, s1>>>();
    k_hist_ee<<<1024, 256, 0, s1>>>(eei);
    k_scan_col<<<1, 1024, 0, s1>>>();
    cudaEventRecord(evScanC, s1);
    k_scatter_ee<<<1024, 256, 0, s1>>>(eei);
    cudaEventRecord(evScatE, s1);

    // branch prep (s2): weights + x = ne @ W_hg
    k_prep<<<81, 256, 0, s2>>>(W_gcn, W_lin2, W_lin3, W_out, b_gcn, b_lin2, b_lin3, b_out);
    k_xgemm<<<256, 256, 0, s2>>>(node_embeds, W_hg);
    cudaEventRecord(evPrep, s2);

    // spine (default): zero -> hist_he -> scan_he -> scatter_he -> accA
    k_zero_he<<<256, 256>>>();
    k_hist_he<<<1024, 256>>>(ei);
    k_scan_he<<<1, 1024>>>();
    k_scatter_he<<<1024, 256>>>(ei);
    k_accA<<<8192, 256>>>();

    // chain needs L (accA), g_dinv (scan_he), x + Wg2 (s2)
    cudaStreamWaitEvent(0, evPrep, 0);
    k_chain<<<256, 256>>>(b_hg, W_lin, b_lin);

    // k_u needs T16 (chain), he CSR, g_dis (scan_col)
    cudaStreamWaitEvent(0, evScanC, 0);
    k_u<<<8192, 256>>>();

    // k_agg needs g_w (k_u), ee CSR (scatter_ee), g_b2 (prep, already joined)
    cudaStreamWaitEvent(0, evScatE, 0);
    k_agg<<<8192, 256>>>();

    k_motif<<<2048, 256, 32 * SMH_STRIDE * 2>>>(mei, out);
}